// round 11
// baseline (speedup 1.0000x reference)
#include <cuda_runtime.h>
#include <cstdint>

// ---------------- problem constants ----------------
#define NN   65536
#define MM   65536
#define HH   128
#define BB   64
#define OUTD 2
#define ALPHA 0.9f
#define EMAX (1 << 20)

// ---------------- device scratch ----------------
__device__ float g_base_x0 [(size_t)NN * HH];
__device__ float g_base_x1 [(size_t)NN * HH];
__device__ float g_base_agg[(size_t)NN * HH];
__device__ float g_local_x0[(size_t)MM * HH];
__device__ float g_local_x1[(size_t)MM * HH];
__device__ float g_local_agg[(size_t)MM * HH];
__device__ float g_sub[BB * HH];
__device__ float g_cnt[BB];

__device__ int   g_csr_cnt [2][NN];
__device__ int   g_csr_ptr [2][NN + 1];
__device__ int   g_csr_fill[2][NN];
__device__ int   g_csr_src [2][EMAX];
__device__ float g_csr_w   [2][EMAX];
__device__ int   g_chunks  [2][256];

// =============== tf32x3 GEMM via mma.sync (sm_80+ ISA, legal on sm_103) ===============
// C[128x128 tile] = relu(A' @ W + bias);  A' = A  or  ALPHA*A + (1-ALPHA)*BX[c2o[row]]
// D = Ah*Bh + Ah*Bl + Al*Bh  (tf32 splits, fp32 accumulate) -> rel err ~1e-6
//
// smem: fragment-permuted operand stores so the mainloop does plain vector LDS:
//   AF[tm 0..7][ks 0..7][lane 0..31][reg 0..3]   (hi, lo)  -> 32KB each
//   BF[tn 0..15][ks 0..7][lane 0..31][reg 0..1]  (hi, lo)  -> 32KB each
// total 131072 B -> 1 CTA/SM.
#define MMA_SMEM 131072

__device__ __forceinline__ uint32_t f2tf32(float v) {
    uint32_t r;
    asm("cvt.rna.tf32.f32 %0, %1;" : "=r"(r) : "f"(v));
    return r;
}

__device__ __forceinline__ void mma_tf32(float* d, const uint32_t* a, const uint32_t* b) {
    asm volatile(
        "mma.sync.aligned.m16n8k8.row.col.f32.tf32.tf32.f32 "
        "{%0,%1,%2,%3}, {%4,%5,%6,%7}, {%8,%9}, {%0,%1,%2,%3};"
        : "+f"(d[0]), "+f"(d[1]), "+f"(d[2]), "+f"(d[3])
        : "r"(a[0]), "r"(a[1]), "r"(a[2]), "r"(a[3]), "r"(b[0]), "r"(b[1]));
}

template<bool MIX>
__global__ void __launch_bounds__(256, 1)
gemm_mma(const float* __restrict__ A,
         const float* __restrict__ W,        // [k=128][n=128], n contiguous
         const float* __restrict__ bias,
         float* __restrict__ C,
         const float* __restrict__ BX,
         const int* __restrict__ c2o)
{
    extern __shared__ uint32_t smem[];
    uint32_t* sAhi = smem;                // 8192
    uint32_t* sAlo = smem + 8192;
    uint32_t* sBhi = smem + 16384;
    uint32_t* sBlo = smem + 24576;

    const int tid  = threadIdx.x;
    const int lane = tid & 31;
    const int wid  = tid >> 5;
    const int wm   = wid >> 1;            // 0..3  (m position)
    const int wn   = wid & 1;             // 0..1  (n position)
    const int row0 = blockIdx.x * 128;

    float acc[2][8][4];
    #pragma unroll
    for (int mi = 0; mi < 2; mi++)
        #pragma unroll
        for (int ni = 0; ni < 8; ni++)
            #pragma unroll
            for (int c = 0; c < 4; c++) acc[mi][ni][c] = 0.f;

    const float4* A4 = (const float4*)(A + (size_t)row0 * HH);
    const float4* W4 = (const float4*)W;

    #pragma unroll 1
    for (int h = 0; h < 2; h++) {
        if (h) __syncthreads();            // previous mainloop finished reading smem

        // ---- stage A slice (128 rows x 64 k) into fragment layout, hi/lo ----
        #pragma unroll
        for (int i = 0; i < 8; i++) {
            int idx = tid + 256 * i;       // 0..2047
            int r   = idx >> 4;            // row in tile 0..127
            int q   = idx & 15;            // float4 index within the 64-k half
            float4 v = A4[r * 32 + h * 16 + q];
            if (MIX) {
                int o = __ldg(&c2o[row0 + r]);
                float4 b = ((const float4*)BX)[(size_t)o * 32 + h * 16 + q];
                v.x = ALPHA * v.x + (1.0f - ALPHA) * b.x;
                v.y = ALPHA * v.y + (1.0f - ALPHA) * b.y;
                v.z = ALPHA * v.z + (1.0f - ALPHA) * b.z;
                v.w = ALPHA * v.w + (1.0f - ALPHA) * b.w;
            }
            int kk    = q * 4;             // local k of v.x
            int tm    = r >> 4;
            int rt    = r & 15;
            int g     = rt & 7;
            int rh    = rt >> 3;           // a0/a1 vs a2/a3 row half
            int ks    = kk >> 3;
            int khalf = (kk >> 2) & 1;     // k<4 -> a0/a1 ; k>=4 -> a2/a3
            int reg   = khalf * 2 + rh;
            int base  = ((tm * 8 + ks) * 32 + 4 * g) * 4 + reg;
            float e[4] = {v.x, v.y, v.z, v.w};
            #pragma unroll
            for (int j = 0; j < 4; j++) {
                uint32_t hi = f2tf32(e[j]);
                uint32_t lo = f2tf32(e[j] - __uint_as_float(hi));
                sAhi[base + 4 * j] = hi;
                sAlo[base + 4 * j] = lo;
            }
        }
        // ---- stage B slice = W[64h:64h+64][0:128] into fragment layout, hi/lo ----
        #pragma unroll
        for (int i = 0; i < 8; i++) {
            int idx = tid + 256 * i;       // 0..2047
            int kk  = idx >> 5;            // local k 0..63
            int q   = idx & 31;            // float4 along n
            float4 v = W4[(h * 64 + kk) * 32 + q];
            int ks  = kk >> 3;
            int tig = kk & 3;
            int reg = (kk >> 2) & 1;       // b0 (k<4) / b1 (k>=4)
            float e[4] = {v.x, v.y, v.z, v.w};
            #pragma unroll
            for (int j = 0; j < 4; j++) {
                int n  = 4 * q + j;
                int tn = n >> 3;
                int gg = n & 7;
                int id = ((tn * 8 + ks) * 32 + 4 * gg + tig) * 2 + reg;
                uint32_t hi = f2tf32(e[j]);
                uint32_t lo = f2tf32(e[j] - __uint_as_float(hi));
                sBhi[id] = hi;
                sBlo[id] = lo;
            }
        }
        __syncthreads();

        // ---- mainloop: 8 ksteps of m16n8k8, 3 terms ----
        #pragma unroll 2
        for (int ks = 0; ks < 8; ks++) {
            uint32_t ah[2][4], al[2][4], bh[8][2], bl[8][2];
            #pragma unroll
            for (int mi = 0; mi < 2; mi++) {
                int off = (((wm * 2 + mi) * 8 + ks) * 32 + lane) * 4;
                *(uint4*)ah[mi] = *(const uint4*)&sAhi[off];
                *(uint4*)al[mi] = *(const uint4*)&sAlo[off];
            }
            #pragma unroll
            for (int ni = 0; ni < 8; ni++) {
                int off = (((wn * 8 + ni) * 8 + ks) * 32 + lane) * 2;
                *(uint2*)bh[ni] = *(const uint2*)&sBhi[off];
                *(uint2*)bl[ni] = *(const uint2*)&sBlo[off];
            }
            #pragma unroll
            for (int mi = 0; mi < 2; mi++)
                #pragma unroll
                for (int ni = 0; ni < 8; ni++) {
                    mma_tf32(acc[mi][ni], ah[mi], bh[ni]);
                    mma_tf32(acc[mi][ni], ah[mi], bl[ni]);
                    mma_tf32(acc[mi][ni], al[mi], bh[ni]);
                }
        }
    }

    // ---- epilogue: bias + relu, direct stores ----
    const int g   = lane >> 2;
    const int tig = lane & 3;
    #pragma unroll
    for (int mi = 0; mi < 2; mi++) {
        int row_a = row0 + (wm * 2 + mi) * 16 + g;
        #pragma unroll
        for (int ni = 0; ni < 8; ni++) {
            int col = wn * 64 + ni * 8 + 2 * tig;
            float b0 = __ldg(&bias[col]);
            float b1 = __ldg(&bias[col + 1]);
            float2 o0, o1;
            o0.x = fmaxf(acc[mi][ni][0] + b0, 0.f);
            o0.y = fmaxf(acc[mi][ni][1] + b1, 0.f);
            o1.x = fmaxf(acc[mi][ni][2] + b0, 0.f);
            o1.y = fmaxf(acc[mi][ni][3] + b1, 0.f);
            *(float2*)&C[(size_t)row_a * HH + col]       = o0;
            *(float2*)&C[(size_t)(row_a + 8) * HH + col] = o1;
        }
    }
}

// ---------------- CSR build ----------------
__global__ void hist_kernel(const int* __restrict__ dst, int* __restrict__ cnt, int E)
{
    int e = blockIdx.x * blockDim.x + threadIdx.x;
    if (e < E) atomicAdd(&cnt[dst[e]], 1);
}

__global__ void chunksum_kernel(const int* __restrict__ cnt, int* __restrict__ chunks)
{
    const int tid = threadIdx.x, lane = tid & 31, w = tid >> 5;
    __shared__ int wsum[8];
    int v = cnt[blockIdx.x * 256 + tid];
    #pragma unroll
    for (int off = 16; off > 0; off >>= 1) v += __shfl_down_sync(0xffffffffu, v, off);
    if (lane == 0) wsum[w] = v;
    __syncthreads();
    if (tid == 0) {
        int s = 0;
        #pragma unroll
        for (int i = 0; i < 8; i++) s += wsum[i];
        chunks[blockIdx.x] = s;
    }
}

__global__ void scan_chunks_kernel(int* __restrict__ chunks, int* __restrict__ ptr, int n)
{
    const int tid = threadIdx.x, lane = tid & 31, w = tid >> 5;
    __shared__ int wsum[8];
    int v = chunks[tid];
    int inc = v;
    #pragma unroll
    for (int off = 1; off < 32; off <<= 1) {
        int t = __shfl_up_sync(0xffffffffu, inc, off);
        if (lane >= off) inc += t;
    }
    if (lane == 31) wsum[w] = inc;
    __syncthreads();
    if (w == 0 && lane < 8) {
        int s = wsum[lane];
        #pragma unroll
        for (int off = 1; off < 8; off <<= 1) {
            int t = __shfl_up_sync(0x000000ffu, s, off);
            if (lane >= off) s += t;
        }
        wsum[lane] = s;
    }
    __syncthreads();
    int excl = inc - v + (w > 0 ? wsum[w - 1] : 0);
    chunks[tid] = excl;
    if (tid == 255) ptr[n] = excl + v;
}

__global__ void write_ptr_kernel(const int* __restrict__ cnt,
                                 const int* __restrict__ chunks,
                                 int* __restrict__ ptr)
{
    const int tid = threadIdx.x, lane = tid & 31, w = tid >> 5;
    __shared__ int wsum[8];
    const int gid = blockIdx.x * 256 + tid;
    int v = cnt[gid];
    int inc = v;
    #pragma unroll
    for (int off = 1; off < 32; off <<= 1) {
        int t = __shfl_up_sync(0xffffffffu, inc, off);
        if (lane >= off) inc += t;
    }
    if (lane == 31) wsum[w] = inc;
    __syncthreads();
    if (w == 0 && lane < 8) {
        int s = wsum[lane];
        #pragma unroll
        for (int off = 1; off < 8; off <<= 1) {
            int t = __shfl_up_sync(0x000000ffu, s, off);
            if (lane >= off) s += t;
        }
        wsum[lane] = s;
    }
    __syncthreads();
    ptr[gid] = inc - v + (w > 0 ? wsum[w - 1] : 0) + chunks[blockIdx.x];
}

__global__ void scatter_kernel(const int* __restrict__ src,
                               const int* __restrict__ dst,
                               const float* __restrict__ w,
                               const int* __restrict__ ptr,
                               int* __restrict__ fill,
                               int* __restrict__ csrc,
                               float* __restrict__ cw, int E)
{
    int e = blockIdx.x * blockDim.x + threadIdx.x;
    if (e >= E) return;
    int d = dst[e];
    int pos = ptr[d] + atomicAdd(&fill[d], 1);
    csrc[pos] = src[e];
    cw[pos]   = w[e];
}

// ---------------- SpMM over CSR: one warp per destination row ----------------
__global__ void __launch_bounds__(256, 8)
spmm_csr(const float* __restrict__ X,
         const int* __restrict__ ptr,
         const int* __restrict__ csrc,
         const float* __restrict__ cw,
         float* __restrict__ Y, int n)
{
    const int lane = threadIdx.x & 31;
    const int row  = (blockIdx.x * blockDim.x + threadIdx.x) >> 5;
    if (row >= n) return;
    const int beg = ptr[row];
    const int end = ptr[row + 1];
    float4 acc0 = make_float4(0.f, 0.f, 0.f, 0.f);
    float4 acc1 = make_float4(0.f, 0.f, 0.f, 0.f);
    int i = beg;
    for (; i + 1 < end; i += 2) {
        int   s0 = csrc[i];     float w0 = cw[i];
        int   s1 = csrc[i + 1]; float w1 = cw[i + 1];
        float4 v0 = *(const float4*)&X[(size_t)s0 * HH + lane * 4];
        float4 v1 = *(const float4*)&X[(size_t)s1 * HH + lane * 4];
        acc0.x = fmaf(w0, v0.x, acc0.x); acc0.y = fmaf(w0, v0.y, acc0.y);
        acc0.z = fmaf(w0, v0.z, acc0.z); acc0.w = fmaf(w0, v0.w, acc0.w);
        acc1.x = fmaf(w1, v1.x, acc1.x); acc1.y = fmaf(w1, v1.y, acc1.y);
        acc1.z = fmaf(w1, v1.z, acc1.z); acc1.w = fmaf(w1, v1.w, acc1.w);
    }
    if (i < end) {
        int s = csrc[i]; float w = cw[i];
        float4 v = *(const float4*)&X[(size_t)s * HH + lane * 4];
        acc0.x = fmaf(w, v.x, acc0.x); acc0.y = fmaf(w, v.y, acc0.y);
        acc0.z = fmaf(w, v.z, acc0.z); acc0.w = fmaf(w, v.w, acc0.w);
    }
    acc0.x += acc1.x; acc0.y += acc1.y; acc0.z += acc1.z; acc0.w += acc1.w;
    *(float4*)&Y[(size_t)row * HH + lane * 4] = acc0;
}

// ---------------- pooling ----------------
__global__ void pool_kernel(const float* __restrict__ lx,
                            const int* __restrict__ midx,
                            const int* __restrict__ mgid,
                            float* __restrict__ gsub,
                            float* __restrict__ gcnt,
                            int K, int entries_per_block)
{
    __shared__ float acc[BB * HH];
    __shared__ float cnt[BB];
    const int tid = threadIdx.x;
    for (int i = tid; i < BB * HH; i += blockDim.x) acc[i] = 0.f;
    if (tid < BB) cnt[tid] = 0.f;
    __syncthreads();

    const int warp = tid >> 5;
    const int lane = tid & 31;
    const int base = blockIdx.x * entries_per_block;
    const int end  = min(base + entries_per_block, K);
    for (int k = base + warp; k < end; k += (int)(blockDim.x >> 5)) {
        int idx = midx[k];
        int g   = mgid[k];
        float4 v = *(const float4*)&lx[(size_t)idx * HH + lane * 4];
        atomicAdd(&acc[g * HH + lane * 4 + 0], v.x);
        atomicAdd(&acc[g * HH + lane * 4 + 1], v.y);
        atomicAdd(&acc[g * HH + lane * 4 + 2], v.z);
        atomicAdd(&acc[g * HH + lane * 4 + 3], v.w);
        if (lane == 0) atomicAdd(&cnt[g], 1.f);
    }
    __syncthreads();

    for (int i = tid; i < BB * HH; i += blockDim.x)
        if (acc[i] != 0.f) atomicAdd(&gsub[i], acc[i]);
    if (tid < BB && cnt[tid] != 0.f) atomicAdd(&gcnt[tid], cnt[tid]);
}

__global__ void final_kernel(const float* __restrict__ gsub,
                             const float* __restrict__ gcnt,
                             const float* __restrict__ Wp,
                             const float* __restrict__ bp,
                             float* __restrict__ out)
{
    int t = threadIdx.x;
    if (t >= BB * OUTD) return;
    int b = t >> 1, o = t & 1;
    float c = fmaxf(gcnt[b], 1.f);
    float s = 0.f;
    #pragma unroll 8
    for (int h = 0; h < HH; h++) s = fmaf(gsub[b * HH + h], Wp[h * OUTD + o], s);
    out[t] = s / c + bp[o];
}

// ---------------- persistent stream/event resources ----------------
static cudaStream_t g_s1 = nullptr;
static cudaEvent_t  g_ev[8];

// ---------------- host orchestration: two-stream fork/join ----------------
extern "C" void kernel_launch(void* const* d_in, const int* in_sizes, int n_in,
                              void* d_out, int out_size)
{
    const float* x    = (const float*)d_in[0];
    const int*   ei   = (const int*)  d_in[1];
    const float* ew   = (const float*)d_in[2];
    const float* lx0i = (const float*)d_in[3];
    const int*   c2o  = (const int*)  d_in[4];
    const int*   lei  = (const int*)  d_in[5];
    const float* lev  = (const float*)d_in[6];
    const int*   midx = (const int*)  d_in[7];
    const int*   mgid = (const int*)  d_in[8];
    const float* Wb    = (const float*)d_in[10];
    const float* bb    = (const float*)d_in[11];
    const float* Wl    = (const float*)d_in[12];
    const float* bl    = (const float*)d_in[13];
    const float* Wbase = (const float*)d_in[14];
    const float* bbase = (const float*)d_in[15];
    const float* Wloc  = (const float*)d_in[16];
    const float* bloc  = (const float*)d_in[17];
    const float* Wp    = (const float*)d_in[18];
    const float* bp    = (const float*)d_in[19];
    float* out = (float*)d_out;

    const int N  = in_sizes[0] / HH;
    const int M  = in_sizes[3] / HH;
    const int E  = in_sizes[1] / 2;
    const int EL = in_sizes[5] / 2;
    const int K  = in_sizes[7];
    const int L  = in_sizes[14] / (HH * HH);

    if (!g_s1) {
        cudaStreamCreateWithFlags(&g_s1, cudaStreamNonBlocking);
        for (int i = 0; i < 8; i++)
            cudaEventCreateWithFlags(&g_ev[i], cudaEventDisableTiming);
    }
    cudaStream_t D = 0, S = g_s1;

    float *bx0, *bx1, *bagg, *lxA, *lxB, *lagg, *sub, *cntp;
    cudaGetSymbolAddress((void**)&bx0,  g_base_x0);
    cudaGetSymbolAddress((void**)&bx1,  g_base_x1);
    cudaGetSymbolAddress((void**)&bagg, g_base_agg);
    cudaGetSymbolAddress((void**)&lxA,  g_local_x0);
    cudaGetSymbolAddress((void**)&lxB,  g_local_x1);
    cudaGetSymbolAddress((void**)&lagg, g_local_agg);
    cudaGetSymbolAddress((void**)&sub,  g_sub);
    cudaGetSymbolAddress((void**)&cntp, g_cnt);

    int *csr_cnt, *csr_ptr, *csr_fill, *csr_src, *chunks;
    float* csr_w;
    cudaGetSymbolAddress((void**)&csr_cnt,  g_csr_cnt);
    cudaGetSymbolAddress((void**)&csr_ptr,  g_csr_ptr);
    cudaGetSymbolAddress((void**)&csr_fill, g_csr_fill);
    cudaGetSymbolAddress((void**)&csr_src,  g_csr_src);
    cudaGetSymbolAddress((void**)&csr_w,    g_csr_w);
    cudaGetSymbolAddress((void**)&chunks,   g_chunks);

    int*   cnt_b  = csr_cnt;            int*   cnt_l  = csr_cnt + NN;
    int*   ptr_b  = csr_ptr;            int*   ptr_l  = csr_ptr + (NN + 1);
    int*   fill_b = csr_fill;           int*   fill_l = csr_fill + NN;
    int*   src_b  = csr_src;            int*   src_l  = csr_src + EMAX;
    float* w_b    = csr_w;              float* w_l    = csr_w + EMAX;
    int*   chk_b  = chunks;             int*   chk_l  = chunks + 256;

    cudaFuncSetAttribute(gemm_mma<false>,
                         cudaFuncAttributeMaxDynamicSharedMemorySize, (int)MMA_SMEM);
    cudaFuncSetAttribute(gemm_mma<true>,
                         cudaFuncAttributeMaxDynamicSharedMemorySize, (int)MMA_SMEM);

    const int gb_N = N / 128;
    const int gb_M = M / 128;
    const int eb = (E  + 255) / 256;
    const int el = (EL + 255) / 256;
    const int spmm_blocks_N = (N * 32 + 255) / 256;
    const int spmm_blocks_M = (M * 32 + 255) / 256;

    // ---- fork S from D ----
    cudaEventRecord(g_ev[0], D);
    cudaStreamWaitEvent(S, g_ev[0], 0);

    // ---- S: input projections (tensor-pipe) ----
    gemm_mma<false><<<gb_N, 256, MMA_SMEM, S>>>(x,    Wb, bb, bx0, nullptr, nullptr);
    cudaEventRecord(g_ev[1], S);
    gemm_mma<false><<<gb_M, 256, MMA_SMEM, S>>>(lx0i, Wl, bl, lxA, nullptr, nullptr);

    // ---- D: CSR build (mem-bound), local graph first ----
    cudaMemsetAsync(csr_cnt,  0, 2 * NN * sizeof(int), D);
    cudaMemsetAsync(csr_fill, 0, 2 * NN * sizeof(int), D);
    hist_kernel<<<el, 256, 0, D>>>(lei + EL, cnt_l, EL);
    chunksum_kernel<<<256, 256, 0, D>>>(cnt_l, chk_l);
    scan_chunks_kernel<<<1, 256, 0, D>>>(chk_l, ptr_l, M);
    write_ptr_kernel<<<256, 256, 0, D>>>(cnt_l, chk_l, ptr_l);
    scatter_kernel<<<el, 256, 0, D>>>(lei, lei + EL, lev, ptr_l, fill_l, src_l, w_l, EL);
    cudaEventRecord(g_ev[2], D);
    hist_kernel<<<eb, 256, 0, D>>>(ei + E, cnt_b, E);
    chunksum_kernel<<<256, 256, 0, D>>>(cnt_b, chk_b);
    scan_chunks_kernel<<<1, 256, 0, D>>>(chk_b, ptr_b, N);
    write_ptr_kernel<<<256, 256, 0, D>>>(cnt_b, chk_b, ptr_b);
    scatter_kernel<<<eb, 256, 0, D>>>(ei, ei + E, ew, ptr_b, fill_b, src_b, w_b, E);

    cudaStreamWaitEvent(S, g_ev[2], 0);   // S needs local CSR
    cudaStreamWaitEvent(D, g_ev[1], 0);   // D needs base_x0

    // ---- layer loop: base chain on D, local chain on S ----
    float* b_in = bx0; float* b_out = bx1;
    float* l_in = lxA; float* l_out = lxB;
    for (int l = 0; l < L; l++) {
        spmm_csr<<<spmm_blocks_N, 256, 0, D>>>(b_in, ptr_b, src_b, w_b, bagg, N);
        gemm_mma<false><<<gb_N, 256, MMA_SMEM, D>>>(
            bagg, Wbase + (size_t)l * HH * HH, bbase + (size_t)l * HH, b_out,
            nullptr, nullptr);
        cudaEventRecord(g_ev[4 + l], D);

        spmm_csr<<<spmm_blocks_M, 256, 0, S>>>(l_in, ptr_l, src_l, w_l, lagg, M);
        cudaStreamWaitEvent(S, g_ev[4 + l], 0);
        gemm_mma<true><<<gb_M, 256, MMA_SMEM, S>>>(
            lagg, Wloc + (size_t)l * HH * HH, bloc + (size_t)l * HH, l_out,
            b_out, c2o);

        float* t;
        t = b_in; b_in = b_out; b_out = t;
        t = l_in; l_in = l_out; l_out = t;
    }

    // ---- S: pooling + final projection ----
    cudaMemsetAsync(sub,  0, BB * HH * sizeof(float), S);
    cudaMemsetAsync(cntp, 0, BB * sizeof(float), S);
    const int pool_blocks = 128;
    const int entries_per_block = (K + pool_blocks - 1) / pool_blocks;
    pool_kernel<<<pool_blocks, 256, 0, S>>>(l_in, midx, mgid, sub, cntp, K, entries_per_block);
    final_kernel<<<1, 128, 0, S>>>(sub, cntp, Wp, bp, out);

    // ---- join ----
    cudaEventRecord(g_ev[7], S);
    cudaStreamWaitEvent(D, g_ev[7], 0);
}

// round 13
// speedup vs baseline: 1.4784x; 1.4784x over previous
#include <cuda_runtime.h>
#include <cstdint>

// ---------------- problem constants ----------------
#define NN   65536
#define MM   65536
#define HH   128
#define BB   64
#define OUTD 2
#define ALPHA 0.9f
#define EMAX (1 << 20)

// ---------------- device scratch ----------------
__device__ float g_base_x0 [(size_t)NN * HH];
__device__ float g_base_x1 [(size_t)NN * HH];
__device__ float g_base_agg[(size_t)NN * HH];
__device__ float g_local_x0[(size_t)MM * HH];
__device__ float g_local_x1[(size_t)MM * HH];
__device__ float g_local_agg[(size_t)MM * HH];
__device__ float g_sub[BB * HH];
__device__ float g_cnt[BB];

__device__ int   g_csr_cnt [2][NN];
__device__ int   g_csr_ptr [2][NN + 1];
__device__ int   g_csr_fill[2][NN];
__device__ int   g_csr_src [2][EMAX];
__device__ float g_csr_w   [2][EMAX];
__device__ int   g_chunks  [2][256];

// ---------------- GEMM: C[128x128 tile] = relu(A' @ W[128x128] + bias) ----------------
// 512 threads, 4x8 microtile, FFMA2 math, 1 CTA/SM (4 warps/SMSP).
// Round-4 VERIFIED staging layout: As[128][132], swizzle r ^ (8*((k>>2)&15)).
//   - store column rs = r ^ (8*(k4&15)) stays < 128 < AS_LD for all r (fixes R12 bug)
//   - 4-row read run never crosses an 8-boundary -> (tr+i)^X = (tr^X)+i, 16B aligned
// W staged once per 128 rows (half the staging of the 64-row round-7 version).
#define AS_LD 132
#define GEMM_SMEM ((128 * AS_LD + 128 * 128) * sizeof(float))   // 67584+65536 = 133120 B

__device__ __forceinline__ void ffma2(unsigned long long& d,
                                      unsigned long long a,
                                      unsigned long long b)
{
    asm("fma.rn.f32x2 %0, %1, %2, %0;" : "+l"(d) : "l"(a), "l"(b));
}

__device__ __forceinline__ unsigned long long dup_reg(float x)
{
    unsigned long long r;
    asm("mov.b64 %0, {%1, %1};" : "=l"(r) : "r"(__float_as_uint(x)));
    return r;
}

template<bool MIX>
__global__ void __launch_bounds__(512, 1)
gemm128_bias_relu(const float* __restrict__ A,
                  const float* __restrict__ W,
                  const float* __restrict__ bias,
                  float* __restrict__ C,
                  const float* __restrict__ BX,
                  const int* __restrict__ c2o)
{
    extern __shared__ float smem[];
    float* As = smem;                   // [128][AS_LD]  As[k][r ^ swz(k)]
    float* Ws = smem + 128 * AS_LD;     // [128][128]    Ws[k][col]

    const int tid  = threadIdx.x;
    const int row0 = blockIdx.x * 128;

    // ---- stage W (4096 float4), 8 per thread, coalesced ----
    {
        const float4* W4  = (const float4*)W;
        float4*       Ws4 = (float4*)Ws;
        #pragma unroll
        for (int i = 0; i < 8; i++) Ws4[tid + 512 * i] = W4[tid + 512 * i];
    }
    // ---- stage A tile (128 rows) transposed + swizzled (optional alpha-mix) ----
    {
        const float4* A4 = (const float4*)(A + (size_t)row0 * HH);
        #pragma unroll
        for (int i = 0; i < 8; i++) {
            int idx = tid + 512 * i;      // = r*32 + k4 (warp: one row, lanes = k4)
            int r   = idx >> 5;           // 0..127
            int k4  = idx & 31;
            float4 v = A4[idx];
            if (MIX) {
                int o = __ldg(&c2o[row0 + r]);
                float4 b = *(const float4*)&BX[(size_t)o * HH + k4 * 4];
                v.x = ALPHA * v.x + (1.0f - ALPHA) * b.x;
                v.y = ALPHA * v.y + (1.0f - ALPHA) * b.y;
                v.z = ALPHA * v.z + (1.0f - ALPHA) * b.z;
                v.w = ALPHA * v.w + (1.0f - ALPHA) * b.w;
            }
            int rs = r ^ (8 * (k4 & 15));     // swz(k)=8*((k>>2)&15), k=4*k4+q; rs<128
            As[(4 * k4 + 0) * AS_LD + rs] = v.x;
            As[(4 * k4 + 1) * AS_LD + rs] = v.y;
            As[(4 * k4 + 2) * AS_LD + rs] = v.z;
            As[(4 * k4 + 3) * AS_LD + rs] = v.w;
        }
    }
    __syncthreads();

    const int j  = tid & 15;            // column group
    const int tr = (tid >> 4) * 4;      // row offset (0..124)
    const int c0 = 4 * j;               // cols c0..c0+3
    const int c1 = 64 + 4 * j;          // cols c1..c1+3

    unsigned long long acc2[4][4];
    #pragma unroll
    for (int m = 0; m < 4; m++)
        #pragma unroll
        for (int p = 0; p < 4; p++) acc2[m][p] = 0ull;

    #pragma unroll 4
    for (int k = 0; k < 128; k++) {
        const int ab = tr ^ (8 * ((k >> 2) & 15));   // 4-aligned, run of 4 safe
        float4 a0 = *(const float4*)&As[k * AS_LD + ab];        // rows tr..tr+3
        ulonglong2 w0 = *(const ulonglong2*)&Ws[k * 128 + c0];
        ulonglong2 w1 = *(const ulonglong2*)&Ws[k * 128 + c1];

        unsigned long long a2[4];
        a2[0] = dup_reg(a0.x); a2[1] = dup_reg(a0.y);
        a2[2] = dup_reg(a0.z); a2[3] = dup_reg(a0.w);
        unsigned long long wv[4] = {w0.x, w0.y, w1.x, w1.y};

        #pragma unroll
        for (int m = 0; m < 4; m++)
            #pragma unroll
            for (int p = 0; p < 4; p++)
                ffma2(acc2[m][p], a2[m], wv[p]);
    }

    float4 bv0 = *(const float4*)&bias[c0];
    float4 bv1 = *(const float4*)&bias[c1];

    #pragma unroll
    for (int m = 0; m < 4; m++) {
        float2 p0 = *(float2*)&acc2[m][0];
        float2 p1 = *(float2*)&acc2[m][1];
        float2 p2 = *(float2*)&acc2[m][2];
        float2 p3 = *(float2*)&acc2[m][3];
        float4 o0, o1;
        o0.x = fmaxf(p0.x + bv0.x, 0.f);
        o0.y = fmaxf(p0.y + bv0.y, 0.f);
        o0.z = fmaxf(p1.x + bv0.z, 0.f);
        o0.w = fmaxf(p1.y + bv0.w, 0.f);
        o1.x = fmaxf(p2.x + bv1.x, 0.f);
        o1.y = fmaxf(p2.y + bv1.y, 0.f);
        o1.z = fmaxf(p3.x + bv1.z, 0.f);
        o1.w = fmaxf(p3.y + bv1.w, 0.f);
        float* cp = &C[(size_t)(row0 + tr + m) * HH];
        *(float4*)&cp[c0] = o0;
        *(float4*)&cp[c1] = o1;
    }
}

// ---------------- CSR build ----------------
__global__ void hist_kernel(const int* __restrict__ dst, int* __restrict__ cnt, int E)
{
    int e = blockIdx.x * blockDim.x + threadIdx.x;
    if (e < E) atomicAdd(&cnt[dst[e]], 1);
}

__global__ void chunksum_kernel(const int* __restrict__ cnt, int* __restrict__ chunks)
{
    const int tid = threadIdx.x, lane = tid & 31, w = tid >> 5;
    __shared__ int wsum[8];
    int v = cnt[blockIdx.x * 256 + tid];
    #pragma unroll
    for (int off = 16; off > 0; off >>= 1) v += __shfl_down_sync(0xffffffffu, v, off);
    if (lane == 0) wsum[w] = v;
    __syncthreads();
    if (tid == 0) {
        int s = 0;
        #pragma unroll
        for (int i = 0; i < 8; i++) s += wsum[i];
        chunks[blockIdx.x] = s;
    }
}

__global__ void scan_chunks_kernel(int* __restrict__ chunks, int* __restrict__ ptr, int n)
{
    const int tid = threadIdx.x, lane = tid & 31, w = tid >> 5;
    __shared__ int wsum[8];
    int v = chunks[tid];
    int inc = v;
    #pragma unroll
    for (int off = 1; off < 32; off <<= 1) {
        int t = __shfl_up_sync(0xffffffffu, inc, off);
        if (lane >= off) inc += t;
    }
    if (lane == 31) wsum[w] = inc;
    __syncthreads();
    if (w == 0 && lane < 8) {
        int s = wsum[lane];
        #pragma unroll
        for (int off = 1; off < 8; off <<= 1) {
            int t = __shfl_up_sync(0x000000ffu, s, off);
            if (lane >= off) s += t;
        }
        wsum[lane] = s;
    }
    __syncthreads();
    int excl = inc - v + (w > 0 ? wsum[w - 1] : 0);
    chunks[tid] = excl;
    if (tid == 255) ptr[n] = excl + v;
}

__global__ void write_ptr_kernel(const int* __restrict__ cnt,
                                 const int* __restrict__ chunks,
                                 int* __restrict__ ptr)
{
    const int tid = threadIdx.x, lane = tid & 31, w = tid >> 5;
    __shared__ int wsum[8];
    const int gid = blockIdx.x * 256 + tid;
    int v = cnt[gid];
    int inc = v;
    #pragma unroll
    for (int off = 1; off < 32; off <<= 1) {
        int t = __shfl_up_sync(0xffffffffu, inc, off);
        if (lane >= off) inc += t;
    }
    if (lane == 31) wsum[w] = inc;
    __syncthreads();
    if (w == 0 && lane < 8) {
        int s = wsum[lane];
        #pragma unroll
        for (int off = 1; off < 8; off <<= 1) {
            int t = __shfl_up_sync(0x000000ffu, s, off);
            if (lane >= off) s += t;
        }
        wsum[lane] = s;
    }
    __syncthreads();
    ptr[gid] = inc - v + (w > 0 ? wsum[w - 1] : 0) + chunks[blockIdx.x];
}

__global__ void scatter_kernel(const int* __restrict__ src,
                               const int* __restrict__ dst,
                               const float* __restrict__ w,
                               const int* __restrict__ ptr,
                               int* __restrict__ fill,
                               int* __restrict__ csrc,
                               float* __restrict__ cw, int E)
{
    int e = blockIdx.x * blockDim.x + threadIdx.x;
    if (e >= E) return;
    int d = dst[e];
    int pos = ptr[d] + atomicAdd(&fill[d], 1);
    csrc[pos] = src[e];
    cw[pos]   = w[e];
}

// ---------------- SpMM over CSR: one warp per destination row ----------------
__global__ void __launch_bounds__(256, 8)
spmm_csr(const float* __restrict__ X,
         const int* __restrict__ ptr,
         const int* __restrict__ csrc,
         const float* __restrict__ cw,
         float* __restrict__ Y, int n)
{
    const int lane = threadIdx.x & 31;
    const int row  = (blockIdx.x * blockDim.x + threadIdx.x) >> 5;
    if (row >= n) return;
    const int beg = ptr[row];
    const int end = ptr[row + 1];
    float4 acc0 = make_float4(0.f, 0.f, 0.f, 0.f);
    float4 acc1 = make_float4(0.f, 0.f, 0.f, 0.f);
    int i = beg;
    for (; i + 1 < end; i += 2) {
        int   s0 = csrc[i];     float w0 = cw[i];
        int   s1 = csrc[i + 1]; float w1 = cw[i + 1];
        float4 v0 = *(const float4*)&X[(size_t)s0 * HH + lane * 4];
        float4 v1 = *(const float4*)&X[(size_t)s1 * HH + lane * 4];
        acc0.x = fmaf(w0, v0.x, acc0.x); acc0.y = fmaf(w0, v0.y, acc0.y);
        acc0.z = fmaf(w0, v0.z, acc0.z); acc0.w = fmaf(w0, v0.w, acc0.w);
        acc1.x = fmaf(w1, v1.x, acc1.x); acc1.y = fmaf(w1, v1.y, acc1.y);
        acc1.z = fmaf(w1, v1.z, acc1.z); acc1.w = fmaf(w1, v1.w, acc1.w);
    }
    if (i < end) {
        int s = csrc[i]; float w = cw[i];
        float4 v = *(const float4*)&X[(size_t)s * HH + lane * 4];
        acc0.x = fmaf(w, v.x, acc0.x); acc0.y = fmaf(w, v.y, acc0.y);
        acc0.z = fmaf(w, v.z, acc0.z); acc0.w = fmaf(w, v.w, acc0.w);
    }
    acc0.x += acc1.x; acc0.y += acc1.y; acc0.z += acc1.z; acc0.w += acc1.w;
    *(float4*)&Y[(size_t)row * HH + lane * 4] = acc0;
}

// ---------------- pooling ----------------
__global__ void pool_kernel(const float* __restrict__ lx,
                            const int* __restrict__ midx,
                            const int* __restrict__ mgid,
                            float* __restrict__ gsub,
                            float* __restrict__ gcnt,
                            int K, int entries_per_block)
{
    __shared__ float acc[BB * HH];
    __shared__ float cnt[BB];
    const int tid = threadIdx.x;
    for (int i = tid; i < BB * HH; i += blockDim.x) acc[i] = 0.f;
    if (tid < BB) cnt[tid] = 0.f;
    __syncthreads();

    const int warp = tid >> 5;
    const int lane = tid & 31;
    const int base = blockIdx.x * entries_per_block;
    const int end  = min(base + entries_per_block, K);
    for (int k = base + warp; k < end; k += (int)(blockDim.x >> 5)) {
        int idx = midx[k];
        int g   = mgid[k];
        float4 v = *(const float4*)&lx[(size_t)idx * HH + lane * 4];
        atomicAdd(&acc[g * HH + lane * 4 + 0], v.x);
        atomicAdd(&acc[g * HH + lane * 4 + 1], v.y);
        atomicAdd(&acc[g * HH + lane * 4 + 2], v.z);
        atomicAdd(&acc[g * HH + lane * 4 + 3], v.w);
        if (lane == 0) atomicAdd(&cnt[g], 1.f);
    }
    __syncthreads();

    for (int i = tid; i < BB * HH; i += blockDim.x)
        if (acc[i] != 0.f) atomicAdd(&gsub[i], acc[i]);
    if (tid < BB && cnt[tid] != 0.f) atomicAdd(&gcnt[tid], cnt[tid]);
}

__global__ void final_kernel(const float* __restrict__ gsub,
                             const float* __restrict__ gcnt,
                             const float* __restrict__ Wp,
                             const float* __restrict__ bp,
                             float* __restrict__ out)
{
    int t = threadIdx.x;
    if (t >= BB * OUTD) return;
    int b = t >> 1, o = t & 1;
    float c = fmaxf(gcnt[b], 1.f);
    float s = 0.f;
    #pragma unroll 8
    for (int h = 0; h < HH; h++) s = fmaf(gsub[b * HH + h], Wp[h * OUTD + o], s);
    out[t] = s / c + bp[o];
}

// ---------------- persistent stream/event resources ----------------
static cudaStream_t g_s1 = nullptr;
static cudaEvent_t  g_ev[8];

// ---------------- host orchestration: two-stream fork/join ----------------
extern "C" void kernel_launch(void* const* d_in, const int* in_sizes, int n_in,
                              void* d_out, int out_size)
{
    const float* x    = (const float*)d_in[0];
    const int*   ei   = (const int*)  d_in[1];
    const float* ew   = (const float*)d_in[2];
    const float* lx0i = (const float*)d_in[3];
    const int*   c2o  = (const int*)  d_in[4];
    const int*   lei  = (const int*)  d_in[5];
    const float* lev  = (const float*)d_in[6];
    const int*   midx = (const int*)  d_in[7];
    const int*   mgid = (const int*)  d_in[8];
    const float* Wb    = (const float*)d_in[10];
    const float* bb    = (const float*)d_in[11];
    const float* Wl    = (const float*)d_in[12];
    const float* bl    = (const float*)d_in[13];
    const float* Wbase = (const float*)d_in[14];
    const float* bbase = (const float*)d_in[15];
    const float* Wloc  = (const float*)d_in[16];
    const float* bloc  = (const float*)d_in[17];
    const float* Wp    = (const float*)d_in[18];
    const float* bp    = (const float*)d_in[19];
    float* out = (float*)d_out;

    const int N  = in_sizes[0] / HH;
    const int M  = in_sizes[3] / HH;
    const int E  = in_sizes[1] / 2;
    const int EL = in_sizes[5] / 2;
    const int K  = in_sizes[7];
    const int L  = in_sizes[14] / (HH * HH);

    if (!g_s1) {
        cudaStreamCreateWithFlags(&g_s1, cudaStreamNonBlocking);
        for (int i = 0; i < 8; i++)
            cudaEventCreateWithFlags(&g_ev[i], cudaEventDisableTiming);
    }
    cudaStream_t D = 0, S = g_s1;

    float *bx0, *bx1, *bagg, *lxA, *lxB, *lagg, *sub, *cntp;
    cudaGetSymbolAddress((void**)&bx0,  g_base_x0);
    cudaGetSymbolAddress((void**)&bx1,  g_base_x1);
    cudaGetSymbolAddress((void**)&bagg, g_base_agg);
    cudaGetSymbolAddress((void**)&lxA,  g_local_x0);
    cudaGetSymbolAddress((void**)&lxB,  g_local_x1);
    cudaGetSymbolAddress((void**)&lagg, g_local_agg);
    cudaGetSymbolAddress((void**)&sub,  g_sub);
    cudaGetSymbolAddress((void**)&cntp, g_cnt);

    int *csr_cnt, *csr_ptr, *csr_fill, *csr_src, *chunks;
    float* csr_w;
    cudaGetSymbolAddress((void**)&csr_cnt,  g_csr_cnt);
    cudaGetSymbolAddress((void**)&csr_ptr,  g_csr_ptr);
    cudaGetSymbolAddress((void**)&csr_fill, g_csr_fill);
    cudaGetSymbolAddress((void**)&csr_src,  g_csr_src);
    cudaGetSymbolAddress((void**)&csr_w,    g_csr_w);
    cudaGetSymbolAddress((void**)&chunks,   g_chunks);

    int*   cnt_b  = csr_cnt;            int*   cnt_l  = csr_cnt + NN;
    int*   ptr_b  = csr_ptr;            int*   ptr_l  = csr_ptr + (NN + 1);
    int*   fill_b = csr_fill;           int*   fill_l = csr_fill + NN;
    int*   src_b  = csr_src;            int*   src_l  = csr_src + EMAX;
    float* w_b    = csr_w;              float* w_l    = csr_w + EMAX;
    int*   chk_b  = chunks;             int*   chk_l  = chunks + 256;

    cudaFuncSetAttribute(gemm128_bias_relu<false>,
                         cudaFuncAttributeMaxDynamicSharedMemorySize, (int)GEMM_SMEM);
    cudaFuncSetAttribute(gemm128_bias_relu<true>,
                         cudaFuncAttributeMaxDynamicSharedMemorySize, (int)GEMM_SMEM);

    const int gb_N = N / 128;
    const int gb_M = M / 128;
    const int eb = (E  + 255) / 256;
    const int el = (EL + 255) / 256;
    const int spmm_blocks_N = (N * 32 + 255) / 256;
    const int spmm_blocks_M = (M * 32 + 255) / 256;

    // ---- fork S from D ----
    cudaEventRecord(g_ev[0], D);
    cudaStreamWaitEvent(S, g_ev[0], 0);

    // ---- S: input projections (FMA-bound) ----
    gemm128_bias_relu<false><<<gb_N, 512, GEMM_SMEM, S>>>(
        x,    Wb, bb, bx0, nullptr, nullptr);
    cudaEventRecord(g_ev[1], S);
    gemm128_bias_relu<false><<<gb_M, 512, GEMM_SMEM, S>>>(
        lx0i, Wl, bl, lxA, nullptr, nullptr);

    // ---- D: CSR build (mem-bound), local graph first ----
    cudaMemsetAsync(csr_cnt,  0, 2 * NN * sizeof(int), D);
    cudaMemsetAsync(csr_fill, 0, 2 * NN * sizeof(int), D);
    hist_kernel<<<el, 256, 0, D>>>(lei + EL, cnt_l, EL);
    chunksum_kernel<<<256, 256, 0, D>>>(cnt_l, chk_l);
    scan_chunks_kernel<<<1, 256, 0, D>>>(chk_l, ptr_l, M);
    write_ptr_kernel<<<256, 256, 0, D>>>(cnt_l, chk_l, ptr_l);
    scatter_kernel<<<el, 256, 0, D>>>(lei, lei + EL, lev, ptr_l, fill_l, src_l, w_l, EL);
    cudaEventRecord(g_ev[2], D);
    hist_kernel<<<eb, 256, 0, D>>>(ei + E, cnt_b, E);
    chunksum_kernel<<<256, 256, 0, D>>>(cnt_b, chk_b);
    scan_chunks_kernel<<<1, 256, 0, D>>>(chk_b, ptr_b, N);
    write_ptr_kernel<<<256, 256, 0, D>>>(cnt_b, chk_b, ptr_b);
    scatter_kernel<<<eb, 256, 0, D>>>(ei, ei + E, ew, ptr_b, fill_b, src_b, w_b, E);

    cudaStreamWaitEvent(S, g_ev[2], 0);   // S needs local CSR
    cudaStreamWaitEvent(D, g_ev[1], 0);   // D needs base_x0

    // ---- layer loop: base chain on D, local chain on S ----
    float* b_in = bx0; float* b_out = bx1;
    float* l_in = lxA; float* l_out = lxB;
    for (int l = 0; l < L; l++) {
        spmm_csr<<<spmm_blocks_N, 256, 0, D>>>(b_in, ptr_b, src_b, w_b, bagg, N);
        gemm128_bias_relu<false><<<gb_N, 512, GEMM_SMEM, D>>>(
            bagg, Wbase + (size_t)l * HH * HH, bbase + (size_t)l * HH, b_out,
            nullptr, nullptr);
        cudaEventRecord(g_ev[4 + l], D);

        spmm_csr<<<spmm_blocks_M, 256, 0, S>>>(l_in, ptr_l, src_l, w_l, lagg, M);
        cudaStreamWaitEvent(S, g_ev[4 + l], 0);
        gemm128_bias_relu<true><<<gb_M, 512, GEMM_SMEM, S>>>(
            lagg, Wloc + (size_t)l * HH * HH, bloc + (size_t)l * HH, l_out,
            b_out, c2o);

        float* t;
        t = b_in; b_in = b_out; b_out = t;
        t = l_in; l_in = l_out; l_out = t;
    }

    // ---- S: pooling + final projection ----
    cudaMemsetAsync(sub,  0, BB * HH * sizeof(float), S);
    cudaMemsetAsync(cntp, 0, BB * sizeof(float), S);
    const int pool_blocks = 128;
    const int entries_per_block = (K + pool_blocks - 1) / pool_blocks;
    pool_kernel<<<pool_blocks, 256, 0, S>>>(l_in, midx, mgid, sub, cntp, K, entries_per_block);
    final_kernel<<<1, 128, 0, S>>>(sub, cntp, Wp, bp, out);

    // ---- join ----
    cudaEventRecord(g_ev[7], S);
    cudaStreamWaitEvent(D, g_ev[7], 0);
}

// round 14
// speedup vs baseline: 1.6352x; 1.1060x over previous
#include <cuda_runtime.h>
#include <cstdint>

// ---------------- problem constants ----------------
#define NN   65536
#define MM   65536
#define HH   128
#define BB   64
#define OUTD 2
#define ALPHA 0.9f
#define EMAX (1 << 20)

// ---------------- device scratch ----------------
__device__ float g_base_x0 [(size_t)NN * HH];
__device__ float g_base_x1 [(size_t)NN * HH];
__device__ float g_base_agg[(size_t)NN * HH];
__device__ float g_local_x0[(size_t)MM * HH];
__device__ float g_local_x1[(size_t)MM * HH];
__device__ float g_local_agg[(size_t)MM * HH];
__device__ float g_sub[BB * HH];
__device__ float g_cnt[BB];

__device__ int   g_csr_cnt [2][NN];        // contiguous: [0]=base, [1]=local
__device__ int   g_csr_ptr [2][NN + 1];
__device__ int   g_csr_fill[2][NN];
__device__ int   g_csr_src [2][EMAX];
__device__ float g_csr_w   [2][EMAX];
__device__ int   g_chunks  [2][256];       // contiguous 512 chunk slots

// ---------------- GEMM (round-7/9 WIN config): C[64x128] = relu(A' @ W + bias) ----------------
// 256 threads, 4x8 microtile, FFMA2, 96KB smem -> 2 CTAs/SM.
#define GEMM_SMEM ((128 * 64 + 128 * 128) * sizeof(float))   // 98304 B

__device__ __forceinline__ void ffma2(unsigned long long& d,
                                      unsigned long long a,
                                      unsigned long long b)
{
    asm("fma.rn.f32x2 %0, %1, %2, %0;" : "+l"(d) : "l"(a), "l"(b));
}

__device__ __forceinline__ unsigned long long dup_reg(float x)
{
    unsigned long long r;
    asm("mov.b64 %0, {%1, %1};" : "=l"(r) : "r"(__float_as_uint(x)));
    return r;
}

template<bool MIX>
__global__ void __launch_bounds__(256, 2)
gemm128_bias_relu(const float* __restrict__ A,
                  const float* __restrict__ W,
                  const float* __restrict__ bias,
                  float* __restrict__ C,
                  const float* __restrict__ BX,
                  const int* __restrict__ c2o)
{
    extern __shared__ float smem[];
    float* As = smem;                // [128][64]   As[k][r ^ swz(k)]
    float* Ws = smem + 128 * 64;     // [128][128]  Ws[k][col]

    const int tid  = threadIdx.x;
    const int row0 = blockIdx.x * 64;

    {
        const float4* W4  = (const float4*)W;
        float4*       Ws4 = (float4*)Ws;
        #pragma unroll
        for (int i = 0; i < 16; i++) Ws4[tid + 256 * i] = W4[tid + 256 * i];
    }
    {
        const float4* A4 = (const float4*)(A + (size_t)row0 * HH);
        #pragma unroll
        for (int i = 0; i < 8; i++) {
            int idx = tid + 256 * i;      // = r*32 + k4
            int r   = idx >> 5;           // 0..63
            int k4  = idx & 31;
            float4 v = A4[idx];
            if (MIX) {
                int o = __ldg(&c2o[row0 + r]);
                float4 b = *(const float4*)&BX[(size_t)o * HH + k4 * 4];
                v.x = ALPHA * v.x + (1.0f - ALPHA) * b.x;
                v.y = ALPHA * v.y + (1.0f - ALPHA) * b.y;
                v.z = ALPHA * v.z + (1.0f - ALPHA) * b.z;
                v.w = ALPHA * v.w + (1.0f - ALPHA) * b.w;
            }
            int rs = r ^ (4 * (k4 & 15));
            As[(4 * k4 + 0) * 64 + rs] = v.x;
            As[(4 * k4 + 1) * 64 + rs] = v.y;
            As[(4 * k4 + 2) * 64 + rs] = v.z;
            As[(4 * k4 + 3) * 64 + rs] = v.w;
        }
    }
    __syncthreads();

    const int j  = tid & 15;
    const int tr = (tid >> 4) * 4;
    const int c0 = 4 * j;
    const int c1 = 64 + 4 * j;

    unsigned long long acc2[4][4];
    #pragma unroll
    for (int m = 0; m < 4; m++)
        #pragma unroll
        for (int p = 0; p < 4; p++) acc2[m][p] = 0ull;

    #pragma unroll 4
    for (int k = 0; k < 128; k++) {
        const int ab = tr ^ (4 * ((k >> 2) & 15));
        float4 a0 = *(const float4*)&As[k * 64 + ab];
        ulonglong2 w0 = *(const ulonglong2*)&Ws[k * 128 + c0];
        ulonglong2 w1 = *(const ulonglong2*)&Ws[k * 128 + c1];

        unsigned long long a2[4];
        a2[0] = dup_reg(a0.x); a2[1] = dup_reg(a0.y);
        a2[2] = dup_reg(a0.z); a2[3] = dup_reg(a0.w);
        unsigned long long wv[4] = {w0.x, w0.y, w1.x, w1.y};

        #pragma unroll
        for (int m = 0; m < 4; m++)
            #pragma unroll
            for (int p = 0; p < 4; p++)
                ffma2(acc2[m][p], a2[m], wv[p]);
    }

    float4 bv0 = *(const float4*)&bias[c0];
    float4 bv1 = *(const float4*)&bias[c1];

    #pragma unroll
    for (int m = 0; m < 4; m++) {
        float2 p0 = *(float2*)&acc2[m][0];
        float2 p1 = *(float2*)&acc2[m][1];
        float2 p2 = *(float2*)&acc2[m][2];
        float2 p3 = *(float2*)&acc2[m][3];
        float4 o0, o1;
        o0.x = fmaxf(p0.x + bv0.x, 0.f);
        o0.y = fmaxf(p0.y + bv0.y, 0.f);
        o0.z = fmaxf(p1.x + bv0.z, 0.f);
        o0.w = fmaxf(p1.y + bv0.w, 0.f);
        o1.x = fmaxf(p2.x + bv1.x, 0.f);
        o1.y = fmaxf(p2.y + bv1.y, 0.f);
        o1.z = fmaxf(p3.x + bv1.z, 0.f);
        o1.w = fmaxf(p3.y + bv1.w, 0.f);
        float* cp = &C[(size_t)(row0 + tr + m) * HH];
        *(float4*)&cp[c0] = o0;
        *(float4*)&cp[c1] = o1;
    }
}

// ---------------- CSR build, fused across both graphs ----------------
// hist2: one launch over E+EL edges; cnt is the contiguous [2][NN] array.
__global__ void hist2_kernel(const int* __restrict__ dst_b, int E,
                             const int* __restrict__ dst_l, int EL,
                             int* __restrict__ cnt)
{
    int e = blockIdx.x * blockDim.x + threadIdx.x;
    if (e < E)            atomicAdd(&cnt[dst_b[e]], 1);
    else if (e < E + EL)  atomicAdd(&cnt[NN + dst_l[e - E]], 1);
}

// chunksum over 512 chunks (2 graphs x 256)
__global__ void chunksum_kernel(const int* __restrict__ cnt, int* __restrict__ chunks)
{
    const int tid = threadIdx.x, lane = tid & 31, w = tid >> 5;
    __shared__ int wsum[8];
    int v = cnt[blockIdx.x * 256 + tid];
    #pragma unroll
    for (int off = 16; off > 0; off >>= 1) v += __shfl_down_sync(0xffffffffu, v, off);
    if (lane == 0) wsum[w] = v;
    __syncthreads();
    if (tid == 0) {
        int s = 0;
        #pragma unroll
        for (int i = 0; i < 8; i++) s += wsum[i];
        chunks[blockIdx.x] = s;
    }
}

// scan2: grid=2, block g scans its graph's 256 chunk sums in place (exclusive),
// writing the grand total into that graph's ptr[n].
__global__ void scan2_kernel(int* __restrict__ chunks,
                             int* __restrict__ ptr_b, int* __restrict__ ptr_l, int n)
{
    const int g   = blockIdx.x;
    const int tid = threadIdx.x, lane = tid & 31, w = tid >> 5;
    int* ch = chunks + g * 256;
    __shared__ int wsum[8];
    int v = ch[tid];
    int inc = v;
    #pragma unroll
    for (int off = 1; off < 32; off <<= 1) {
        int t = __shfl_up_sync(0xffffffffu, inc, off);
        if (lane >= off) inc += t;
    }
    if (lane == 31) wsum[w] = inc;
    __syncthreads();
    if (w == 0 && lane < 8) {
        int s = wsum[lane];
        #pragma unroll
        for (int off = 1; off < 8; off <<= 1) {
            int t = __shfl_up_sync(0x000000ffu, s, off);
            if (lane >= off) s += t;
        }
        wsum[lane] = s;
    }
    __syncthreads();
    int excl = inc - v + (w > 0 ? wsum[w - 1] : 0);
    ch[tid] = excl;
    if (tid == 255) {
        if (g == 0) ptr_b[n] = excl + v; else ptr_l[n] = excl + v;
    }
}

// write_ptr over 512 blocks: first 256 -> ptr_b, next 256 -> ptr_l
__global__ void write_ptr2_kernel(const int* __restrict__ cnt,
                                  const int* __restrict__ chunks,
                                  int* __restrict__ ptr_b,
                                  int* __restrict__ ptr_l)
{
    const int tid = threadIdx.x, lane = tid & 31, w = tid >> 5;
    __shared__ int wsum[8];
    const int gid = blockIdx.x * 256 + tid;      // 0 .. 2*NN-1
    int v = cnt[gid];
    int inc = v;
    #pragma unroll
    for (int off = 1; off < 32; off <<= 1) {
        int t = __shfl_up_sync(0xffffffffu, inc, off);
        if (lane >= off) inc += t;
    }
    if (lane == 31) wsum[w] = inc;
    __syncthreads();
    if (w == 0 && lane < 8) {
        int s = wsum[lane];
        #pragma unroll
        for (int off = 1; off < 8; off <<= 1) {
            int t = __shfl_up_sync(0x000000ffu, s, off);
            if (lane >= off) s += t;
        }
        wsum[lane] = s;
    }
    __syncthreads();
    int val = inc - v + (w > 0 ? wsum[w - 1] : 0) + chunks[blockIdx.x];
    if (gid < NN) ptr_b[gid] = val;
    else          ptr_l[gid - NN] = val;
}

// scatter2: one launch over E+EL edges
__global__ void scatter2_kernel(const int* __restrict__ ei,  int E,
                                const float* __restrict__ ew,
                                const int* __restrict__ lei, int EL,
                                const float* __restrict__ lev,
                                const int* __restrict__ ptr_b, int* __restrict__ fill_b,
                                int* __restrict__ src_b, float* __restrict__ w_b,
                                const int* __restrict__ ptr_l, int* __restrict__ fill_l,
                                int* __restrict__ src_l, float* __restrict__ w_l)
{
    int e = blockIdx.x * blockDim.x + threadIdx.x;
    if (e < E) {
        int d = ei[E + e];
        int pos = ptr_b[d] + atomicAdd(&fill_b[d], 1);
        src_b[pos] = ei[e];
        w_b[pos]   = ew[e];
    } else if (e < E + EL) {
        int ee = e - E;
        int d = lei[EL + ee];
        int pos = ptr_l[d] + atomicAdd(&fill_l[d], 1);
        src_l[pos] = lei[ee];
        w_l[pos]   = lev[ee];
    }
}

// ---------------- SpMM over CSR: one warp per destination row ----------------
__global__ void __launch_bounds__(256, 8)
spmm_csr(const float* __restrict__ X,
         const int* __restrict__ ptr,
         const int* __restrict__ csrc,
         const float* __restrict__ cw,
         float* __restrict__ Y, int n)
{
    const int lane = threadIdx.x & 31;
    const int row  = (blockIdx.x * blockDim.x + threadIdx.x) >> 5;
    if (row >= n) return;
    const int beg = ptr[row];
    const int end = ptr[row + 1];
    float4 acc0 = make_float4(0.f, 0.f, 0.f, 0.f);
    float4 acc1 = make_float4(0.f, 0.f, 0.f, 0.f);
    int i = beg;
    for (; i + 1 < end; i += 2) {
        int   s0 = csrc[i];     float w0 = cw[i];
        int   s1 = csrc[i + 1]; float w1 = cw[i + 1];
        float4 v0 = *(const float4*)&X[(size_t)s0 * HH + lane * 4];
        float4 v1 = *(const float4*)&X[(size_t)s1 * HH + lane * 4];
        acc0.x = fmaf(w0, v0.x, acc0.x); acc0.y = fmaf(w0, v0.y, acc0.y);
        acc0.z = fmaf(w0, v0.z, acc0.z); acc0.w = fmaf(w0, v0.w, acc0.w);
        acc1.x = fmaf(w1, v1.x, acc1.x); acc1.y = fmaf(w1, v1.y, acc1.y);
        acc1.z = fmaf(w1, v1.z, acc1.z); acc1.w = fmaf(w1, v1.w, acc1.w);
    }
    if (i < end) {
        int s = csrc[i]; float w = cw[i];
        float4 v = *(const float4*)&X[(size_t)s * HH + lane * 4];
        acc0.x = fmaf(w, v.x, acc0.x); acc0.y = fmaf(w, v.y, acc0.y);
        acc0.z = fmaf(w, v.z, acc0.z); acc0.w = fmaf(w, v.w, acc0.w);
    }
    acc0.x += acc1.x; acc0.y += acc1.y; acc0.z += acc1.z; acc0.w += acc1.w;
    *(float4*)&Y[(size_t)row * HH + lane * 4] = acc0;
}

// ---------------- pooling ----------------
__global__ void pool_kernel(const float* __restrict__ lx,
                            const int* __restrict__ midx,
                            const int* __restrict__ mgid,
                            float* __restrict__ gsub,
                            float* __restrict__ gcnt,
                            int K, int entries_per_block)
{
    __shared__ float acc[BB * HH];
    __shared__ float cnt[BB];
    const int tid = threadIdx.x;
    for (int i = tid; i < BB * HH; i += blockDim.x) acc[i] = 0.f;
    if (tid < BB) cnt[tid] = 0.f;
    __syncthreads();

    const int warp = tid >> 5;
    const int lane = tid & 31;
    const int base = blockIdx.x * entries_per_block;
    const int end  = min(base + entries_per_block, K);
    for (int k = base + warp; k < end; k += (int)(blockDim.x >> 5)) {
        int idx = midx[k];
        int g   = mgid[k];
        float4 v = *(const float4*)&lx[(size_t)idx * HH + lane * 4];
        atomicAdd(&acc[g * HH + lane * 4 + 0], v.x);
        atomicAdd(&acc[g * HH + lane * 4 + 1], v.y);
        atomicAdd(&acc[g * HH + lane * 4 + 2], v.z);
        atomicAdd(&acc[g * HH + lane * 4 + 3], v.w);
        if (lane == 0) atomicAdd(&cnt[g], 1.f);
    }
    __syncthreads();

    for (int i = tid; i < BB * HH; i += blockDim.x)
        if (acc[i] != 0.f) atomicAdd(&gsub[i], acc[i]);
    if (tid < BB && cnt[tid] != 0.f) atomicAdd(&gcnt[tid], cnt[tid]);
}

__global__ void final_kernel(const float* __restrict__ gsub,
                             const float* __restrict__ gcnt,
                             const float* __restrict__ Wp,
                             const float* __restrict__ bp,
                             float* __restrict__ out)
{
    int t = threadIdx.x;
    if (t >= BB * OUTD) return;
    int b = t >> 1, o = t & 1;
    float c = fmaxf(gcnt[b], 1.f);
    float s = 0.f;
    #pragma unroll 8
    for (int h = 0; h < HH; h++) s = fmaf(gsub[b * HH + h], Wp[h * OUTD + o], s);
    out[t] = s / c + bp[o];
}

// ---------------- persistent stream/event resources ----------------
static cudaStream_t g_s1 = nullptr;
static cudaEvent_t  g_ev[8];

// ---------------- host orchestration: two-stream fork/join ----------------
extern "C" void kernel_launch(void* const* d_in, const int* in_sizes, int n_in,
                              void* d_out, int out_size)
{
    const float* x    = (const float*)d_in[0];
    const int*   ei   = (const int*)  d_in[1];
    const float* ew   = (const float*)d_in[2];
    const float* lx0i = (const float*)d_in[3];
    const int*   c2o  = (const int*)  d_in[4];
    const int*   lei  = (const int*)  d_in[5];
    const float* lev  = (const float*)d_in[6];
    const int*   midx = (const int*)  d_in[7];
    const int*   mgid = (const int*)  d_in[8];
    const float* Wb    = (const float*)d_in[10];
    const float* bb    = (const float*)d_in[11];
    const float* Wl    = (const float*)d_in[12];
    const float* bl    = (const float*)d_in[13];
    const float* Wbase = (const float*)d_in[14];
    const float* bbase = (const float*)d_in[15];
    const float* Wloc  = (const float*)d_in[16];
    const float* bloc  = (const float*)d_in[17];
    const float* Wp    = (const float*)d_in[18];
    const float* bp    = (const float*)d_in[19];
    float* out = (float*)d_out;

    const int N  = in_sizes[0] / HH;
    const int M  = in_sizes[3] / HH;
    const int E  = in_sizes[1] / 2;
    const int EL = in_sizes[5] / 2;
    const int K  = in_sizes[7];
    const int L  = in_sizes[14] / (HH * HH);

    if (!g_s1) {
        cudaStreamCreateWithFlags(&g_s1, cudaStreamNonBlocking);
        for (int i = 0; i < 8; i++)
            cudaEventCreateWithFlags(&g_ev[i], cudaEventDisableTiming);
    }
    cudaStream_t D = 0, S = g_s1;

    float *bx0, *bx1, *bagg, *lxA, *lxB, *lagg, *sub, *cntp;
    cudaGetSymbolAddress((void**)&bx0,  g_base_x0);
    cudaGetSymbolAddress((void**)&bx1,  g_base_x1);
    cudaGetSymbolAddress((void**)&bagg, g_base_agg);
    cudaGetSymbolAddress((void**)&lxA,  g_local_x0);
    cudaGetSymbolAddress((void**)&lxB,  g_local_x1);
    cudaGetSymbolAddress((void**)&lagg, g_local_agg);
    cudaGetSymbolAddress((void**)&sub,  g_sub);
    cudaGetSymbolAddress((void**)&cntp, g_cnt);

    int *csr_cnt, *csr_ptr, *csr_fill, *csr_src, *chunks;
    float* csr_w;
    cudaGetSymbolAddress((void**)&csr_cnt,  g_csr_cnt);
    cudaGetSymbolAddress((void**)&csr_ptr,  g_csr_ptr);
    cudaGetSymbolAddress((void**)&csr_fill, g_csr_fill);
    cudaGetSymbolAddress((void**)&csr_src,  g_csr_src);
    cudaGetSymbolAddress((void**)&csr_w,    g_csr_w);
    cudaGetSymbolAddress((void**)&chunks,   g_chunks);

    int*   ptr_b  = csr_ptr;            int*   ptr_l  = csr_ptr + (NN + 1);
    int*   fill_b = csr_fill;           int*   fill_l = csr_fill + NN;
    int*   src_b  = csr_src;            int*   src_l  = csr_src + EMAX;
    float* w_b    = csr_w;              float* w_l    = csr_w + EMAX;

    cudaFuncSetAttribute(gemm128_bias_relu<false>,
                         cudaFuncAttributeMaxDynamicSharedMemorySize, (int)GEMM_SMEM);
    cudaFuncSetAttribute(gemm128_bias_relu<true>,
                         cudaFuncAttributeMaxDynamicSharedMemorySize, (int)GEMM_SMEM);

    const int gb_N = N / 64;
    const int gb_M = M / 64;
    const int ET = E + EL;
    const int etb = (ET + 255) / 256;
    const int spmm_blocks_N = (N * 32 + 255) / 256;
    const int spmm_blocks_M = (M * 32 + 255) / 256;

    // ---- fork S from D ----
    cudaEventRecord(g_ev[0], D);
    cudaStreamWaitEvent(S, g_ev[0], 0);

    // ---- S: input projections (FMA-bound) ----
    gemm128_bias_relu<false><<<gb_N, 256, GEMM_SMEM, S>>>(
        x,    Wb, bb, bx0, nullptr, nullptr);
    cudaEventRecord(g_ev[1], S);   // base_x0 ready
    gemm128_bias_relu<false><<<gb_M, 256, GEMM_SMEM, S>>>(
        lx0i, Wl, bl, lxA, nullptr, nullptr);

    // ---- D: CSR build, both graphs fused per phase ----
    cudaMemsetAsync(csr_cnt,  0, 2 * NN * sizeof(int), D);
    cudaMemsetAsync(csr_fill, 0, 2 * NN * sizeof(int), D);
    hist2_kernel<<<etb, 256, 0, D>>>(ei + E, E, lei + EL, EL, csr_cnt);
    chunksum_kernel<<<512, 256, 0, D>>>(csr_cnt, chunks);
    scan2_kernel<<<2, 256, 0, D>>>(chunks, ptr_b, ptr_l, N);
    write_ptr2_kernel<<<512, 256, 0, D>>>(csr_cnt, chunks, ptr_b, ptr_l);
    scatter2_kernel<<<etb, 256, 0, D>>>(ei, E, ew, lei, EL, lev,
                                        ptr_b, fill_b, src_b, w_b,
                                        ptr_l, fill_l, src_l, w_l);
    cudaEventRecord(g_ev[2], D);   // both CSRs ready

    cudaStreamWaitEvent(S, g_ev[2], 0);   // S needs local CSR
    cudaStreamWaitEvent(D, g_ev[1], 0);   // D needs base_x0

    // ---- layer loop: base chain on D, local chain on S ----
    float* b_in = bx0; float* b_out = bx1;
    float* l_in = lxA; float* l_out = lxB;
    for (int l = 0; l < L; l++) {
        spmm_csr<<<spmm_blocks_N, 256, 0, D>>>(b_in, ptr_b, src_b, w_b, bagg, N);
        gemm128_bias_relu<false><<<gb_N, 256, GEMM_SMEM, D>>>(
            bagg, Wbase + (size_t)l * HH * HH, bbase + (size_t)l * HH, b_out,
            nullptr, nullptr);
        cudaEventRecord(g_ev[4 + l], D);

        spmm_csr<<<spmm_blocks_M, 256, 0, S>>>(l_in, ptr_l, src_l, w_l, lagg, M);
        cudaStreamWaitEvent(S, g_ev[4 + l], 0);
        gemm128_bias_relu<true><<<gb_M, 256, GEMM_SMEM, S>>>(
            lagg, Wloc + (size_t)l * HH * HH, bloc + (size_t)l * HH, l_out,
            b_out, c2o);

        float* t;
        t = b_in; b_in = b_out; b_out = t;
        t = l_in; l_in = l_out; l_out = t;
    }

    // ---- S: pooling + final projection ----
    cudaMemsetAsync(sub,  0, BB * HH * sizeof(float), S);
    cudaMemsetAsync(cntp, 0, BB * sizeof(float), S);
    const int pool_blocks = 128;
    const int entries_per_block = (K + pool_blocks - 1) / pool_blocks;
    pool_kernel<<<pool_blocks, 256, 0, S>>>(l_in, midx, mgid, sub, cntp, K, entries_per_block);
    final_kernel<<<1, 128, 0, S>>>(sub, cntp, Wp, bp, out);

    // ---- join ----
    cudaEventRecord(g_ev[7], S);
    cudaStreamWaitEvent(D, g_ev[7], 0);
}

// round 15
// speedup vs baseline: 1.6779x; 1.0261x over previous
#include <cuda_runtime.h>
#include <cstdint>

// ---------------- problem constants ----------------
#define NN   65536
#define MM   65536
#define HH   128
#define BB   64
#define OUTD 2
#define ALPHA 0.9f
#define EMAX (1 << 20)
#define GEMM_GRID 296          // 148 SMs x 2 CTAs (persistent)

// ---------------- device scratch ----------------
__device__ float g_base_x0 [(size_t)NN * HH];
__device__ float g_base_x1 [(size_t)NN * HH];
__device__ float g_base_agg[(size_t)NN * HH];
__device__ float g_local_x0[(size_t)MM * HH];
__device__ float g_local_x1[(size_t)MM * HH];
__device__ float g_local_agg[(size_t)MM * HH];
__device__ float g_sub[BB * HH];
__device__ float g_cnt[BB];

__device__ int   g_csr_cnt [2][NN];        // contiguous: [0]=base, [1]=local
__device__ int   g_csr_ptr [2][NN + 1];
__device__ int   g_csr_fill[2][NN];
__device__ int   g_csr_src [2][EMAX];
__device__ float g_csr_w   [2][EMAX];
__device__ int   g_chunks  [2][256];

// ---------------- persistent GEMM: C[tile 64x128] = relu(A' @ W + bias) ----------------
// 256 threads, 4x8 microtile, FFMA2, 96KB smem -> 2 CTAs/SM.
// W staged ONCE per CTA; CTA grid-strides over tiles (no wave quantization).
#define GEMM_SMEM ((128 * 64 + 128 * 128) * sizeof(float))   // 98304 B

__device__ __forceinline__ void ffma2(unsigned long long& d,
                                      unsigned long long a,
                                      unsigned long long b)
{
    asm("fma.rn.f32x2 %0, %1, %2, %0;" : "+l"(d) : "l"(a), "l"(b));
}

__device__ __forceinline__ unsigned long long dup_reg(float x)
{
    unsigned long long r;
    asm("mov.b64 %0, {%1, %1};" : "=l"(r) : "r"(__float_as_uint(x)));
    return r;
}

template<bool MIX>
__global__ void __launch_bounds__(256, 2)
gemm128_bias_relu(const float* __restrict__ A,
                  const float* __restrict__ W,
                  const float* __restrict__ bias,
                  float* __restrict__ C,
                  const float* __restrict__ BX,
                  const int* __restrict__ c2o,
                  int n_tiles)
{
    extern __shared__ float smem[];
    float* As = smem;                // [128][64]   As[k][r ^ swz(k)]
    float* Ws = smem + 128 * 64;     // [128][128]  Ws[k][col]

    const int tid = threadIdx.x;

    // ---- stage W ONCE per persistent CTA ----
    {
        const float4* W4  = (const float4*)W;
        float4*       Ws4 = (float4*)Ws;
        #pragma unroll
        for (int i = 0; i < 16; i++) Ws4[tid + 256 * i] = W4[tid + 256 * i];
    }

    const int j  = tid & 15;
    const int tr = (tid >> 4) * 4;
    const int c0 = 4 * j;
    const int c1 = 64 + 4 * j;
    float4 bv0 = *(const float4*)&bias[c0];
    float4 bv1 = *(const float4*)&bias[c1];

    for (int t = blockIdx.x; t < n_tiles; t += GEMM_GRID) {
        const int row0 = t * 64;

        // ---- stage A tile transposed + swizzled (optional alpha-mix) ----
        {
            const float4* A4 = (const float4*)(A + (size_t)row0 * HH);
            #pragma unroll
            for (int i = 0; i < 8; i++) {
                int idx = tid + 256 * i;      // = r*32 + k4
                int r   = idx >> 5;           // 0..63
                int k4  = idx & 31;
                float4 v = A4[idx];
                if (MIX) {
                    int o = __ldg(&c2o[row0 + r]);
                    float4 b = *(const float4*)&BX[(size_t)o * HH + k4 * 4];
                    v.x = ALPHA * v.x + (1.0f - ALPHA) * b.x;
                    v.y = ALPHA * v.y + (1.0f - ALPHA) * b.y;
                    v.z = ALPHA * v.z + (1.0f - ALPHA) * b.z;
                    v.w = ALPHA * v.w + (1.0f - ALPHA) * b.w;
                }
                int rs = r ^ (4 * (k4 & 15));
                As[(4 * k4 + 0) * 64 + rs] = v.x;
                As[(4 * k4 + 1) * 64 + rs] = v.y;
                As[(4 * k4 + 2) * 64 + rs] = v.z;
                As[(4 * k4 + 3) * 64 + rs] = v.w;
            }
        }
        __syncthreads();

        unsigned long long acc2[4][4];
        #pragma unroll
        for (int m = 0; m < 4; m++)
            #pragma unroll
            for (int p = 0; p < 4; p++) acc2[m][p] = 0ull;

        #pragma unroll 4
        for (int k = 0; k < 128; k++) {
            const int ab = tr ^ (4 * ((k >> 2) & 15));
            float4 a0 = *(const float4*)&As[k * 64 + ab];
            ulonglong2 w0 = *(const ulonglong2*)&Ws[k * 128 + c0];
            ulonglong2 w1 = *(const ulonglong2*)&Ws[k * 128 + c1];

            unsigned long long a2[4];
            a2[0] = dup_reg(a0.x); a2[1] = dup_reg(a0.y);
            a2[2] = dup_reg(a0.z); a2[3] = dup_reg(a0.w);
            unsigned long long wv[4] = {w0.x, w0.y, w1.x, w1.y};

            #pragma unroll
            for (int m = 0; m < 4; m++)
                #pragma unroll
                for (int p = 0; p < 4; p++)
                    ffma2(acc2[m][p], a2[m], wv[p]);
        }

        #pragma unroll
        for (int m = 0; m < 4; m++) {
            float2 p0 = *(float2*)&acc2[m][0];
            float2 p1 = *(float2*)&acc2[m][1];
            float2 p2 = *(float2*)&acc2[m][2];
            float2 p3 = *(float2*)&acc2[m][3];
            float4 o0, o1;
            o0.x = fmaxf(p0.x + bv0.x, 0.f);
            o0.y = fmaxf(p0.y + bv0.y, 0.f);
            o0.z = fmaxf(p1.x + bv0.z, 0.f);
            o0.w = fmaxf(p1.y + bv0.w, 0.f);
            o1.x = fmaxf(p2.x + bv1.x, 0.f);
            o1.y = fmaxf(p2.y + bv1.y, 0.f);
            o1.z = fmaxf(p3.x + bv1.z, 0.f);
            o1.w = fmaxf(p3.y + bv1.w, 0.f);
            float* cp = &C[(size_t)(row0 + tr + m) * HH];
            *(float4*)&cp[c0] = o0;
            *(float4*)&cp[c1] = o1;
        }
        __syncthreads();   // protect As before next tile's staging
    }
}

// ---------------- CSR build, fused across both graphs ----------------
__global__ void hist2_kernel(const int* __restrict__ dst_b, int E,
                             const int* __restrict__ dst_l, int EL,
                             int* __restrict__ cnt)
{
    int e = blockIdx.x * blockDim.x + threadIdx.x;
    if (e < E)            atomicAdd(&cnt[dst_b[e]], 1);
    else if (e < E + EL)  atomicAdd(&cnt[NN + dst_l[e - E]], 1);
}

__global__ void chunksum_kernel(const int* __restrict__ cnt, int* __restrict__ chunks)
{
    const int tid = threadIdx.x, lane = tid & 31, w = tid >> 5;
    __shared__ int wsum[8];
    int v = cnt[blockIdx.x * 256 + tid];
    #pragma unroll
    for (int off = 16; off > 0; off >>= 1) v += __shfl_down_sync(0xffffffffu, v, off);
    if (lane == 0) wsum[w] = v;
    __syncthreads();
    if (tid == 0) {
        int s = 0;
        #pragma unroll
        for (int i = 0; i < 8; i++) s += wsum[i];
        chunks[blockIdx.x] = s;
    }
}

__global__ void scan2_kernel(int* __restrict__ chunks,
                             int* __restrict__ ptr_b, int* __restrict__ ptr_l, int n)
{
    const int g   = blockIdx.x;
    const int tid = threadIdx.x, lane = tid & 31, w = tid >> 5;
    int* ch = chunks + g * 256;
    __shared__ int wsum[8];
    int v = ch[tid];
    int inc = v;
    #pragma unroll
    for (int off = 1; off < 32; off <<= 1) {
        int t = __shfl_up_sync(0xffffffffu, inc, off);
        if (lane >= off) inc += t;
    }
    if (lane == 31) wsum[w] = inc;
    __syncthreads();
    if (w == 0 && lane < 8) {
        int s = wsum[lane];
        #pragma unroll
        for (int off = 1; off < 8; off <<= 1) {
            int t = __shfl_up_sync(0x000000ffu, s, off);
            if (lane >= off) s += t;
        }
        wsum[lane] = s;
    }
    __syncthreads();
    int excl = inc - v + (w > 0 ? wsum[w - 1] : 0);
    ch[tid] = excl;
    if (tid == 255) {
        if (g == 0) ptr_b[n] = excl + v; else ptr_l[n] = excl + v;
    }
}

__global__ void write_ptr2_kernel(const int* __restrict__ cnt,
                                  const int* __restrict__ chunks,
                                  int* __restrict__ ptr_b,
                                  int* __restrict__ ptr_l)
{
    const int tid = threadIdx.x, lane = tid & 31, w = tid >> 5;
    __shared__ int wsum[8];
    const int gid = blockIdx.x * 256 + tid;
    int v = cnt[gid];
    int inc = v;
    #pragma unroll
    for (int off = 1; off < 32; off <<= 1) {
        int t = __shfl_up_sync(0xffffffffu, inc, off);
        if (lane >= off) inc += t;
    }
    if (lane == 31) wsum[w] = inc;
    __syncthreads();
    if (w == 0 && lane < 8) {
        int s = wsum[lane];
        #pragma unroll
        for (int off = 1; off < 8; off <<= 1) {
            int t = __shfl_up_sync(0x000000ffu, s, off);
            if (lane >= off) s += t;
        }
        wsum[lane] = s;
    }
    __syncthreads();
    int val = inc - v + (w > 0 ? wsum[w - 1] : 0) + chunks[blockIdx.x];
    if (gid < NN) ptr_b[gid] = val;
    else          ptr_l[gid - NN] = val;
}

__global__ void scatter2_kernel(const int* __restrict__ ei,  int E,
                                const float* __restrict__ ew,
                                const int* __restrict__ lei, int EL,
                                const float* __restrict__ lev,
                                const int* __restrict__ ptr_b, int* __restrict__ fill_b,
                                int* __restrict__ src_b, float* __restrict__ w_b,
                                const int* __restrict__ ptr_l, int* __restrict__ fill_l,
                                int* __restrict__ src_l, float* __restrict__ w_l)
{
    int e = blockIdx.x * blockDim.x + threadIdx.x;
    if (e < E) {
        int d = ei[E + e];
        int pos = ptr_b[d] + atomicAdd(&fill_b[d], 1);
        src_b[pos] = ei[e];
        w_b[pos]   = ew[e];
    } else if (e < E + EL) {
        int ee = e - E;
        int d = lei[EL + ee];
        int pos = ptr_l[d] + atomicAdd(&fill_l[d], 1);
        src_l[pos] = lei[ee];
        w_l[pos]   = lev[ee];
    }
}

// ---------------- SpMM over CSR: one warp per destination row ----------------
__global__ void __launch_bounds__(256, 8)
spmm_csr(const float* __restrict__ X,
         const int* __restrict__ ptr,
         const int* __restrict__ csrc,
         const float* __restrict__ cw,
         float* __restrict__ Y, int n)
{
    const int lane = threadIdx.x & 31;
    const int row  = (blockIdx.x * blockDim.x + threadIdx.x) >> 5;
    if (row >= n) return;
    const int beg = ptr[row];
    const int end = ptr[row + 1];
    float4 acc0 = make_float4(0.f, 0.f, 0.f, 0.f);
    float4 acc1 = make_float4(0.f, 0.f, 0.f, 0.f);
    int i = beg;
    for (; i + 1 < end; i += 2) {
        int   s0 = csrc[i];     float w0 = cw[i];
        int   s1 = csrc[i + 1]; float w1 = cw[i + 1];
        float4 v0 = *(const float4*)&X[(size_t)s0 * HH + lane * 4];
        float4 v1 = *(const float4*)&X[(size_t)s1 * HH + lane * 4];
        acc0.x = fmaf(w0, v0.x, acc0.x); acc0.y = fmaf(w0, v0.y, acc0.y);
        acc0.z = fmaf(w0, v0.z, acc0.z); acc0.w = fmaf(w0, v0.w, acc0.w);
        acc1.x = fmaf(w1, v1.x, acc1.x); acc1.y = fmaf(w1, v1.y, acc1.y);
        acc1.z = fmaf(w1, v1.z, acc1.z); acc1.w = fmaf(w1, v1.w, acc1.w);
    }
    if (i < end) {
        int s = csrc[i]; float w = cw[i];
        float4 v = *(const float4*)&X[(size_t)s * HH + lane * 4];
        acc0.x = fmaf(w, v.x, acc0.x); acc0.y = fmaf(w, v.y, acc0.y);
        acc0.z = fmaf(w, v.z, acc0.z); acc0.w = fmaf(w, v.w, acc0.w);
    }
    acc0.x += acc1.x; acc0.y += acc1.y; acc0.z += acc1.z; acc0.w += acc1.w;
    *(float4*)&Y[(size_t)row * HH + lane * 4] = acc0;
}

// ---------------- pooling ----------------
__global__ void pool_kernel(const float* __restrict__ lx,
                            const int* __restrict__ midx,
                            const int* __restrict__ mgid,
                            float* __restrict__ gsub,
                            float* __restrict__ gcnt,
                            int K, int entries_per_block)
{
    __shared__ float acc[BB * HH];
    __shared__ float cnt[BB];
    const int tid = threadIdx.x;
    for (int i = tid; i < BB * HH; i += blockDim.x) acc[i] = 0.f;
    if (tid < BB) cnt[tid] = 0.f;
    __syncthreads();

    const int warp = tid >> 5;
    const int lane = tid & 31;
    const int base = blockIdx.x * entries_per_block;
    const int end  = min(base + entries_per_block, K);
    for (int k = base + warp; k < end; k += (int)(blockDim.x >> 5)) {
        int idx = midx[k];
        int g   = mgid[k];
        float4 v = *(const float4*)&lx[(size_t)idx * HH + lane * 4];
        atomicAdd(&acc[g * HH + lane * 4 + 0], v.x);
        atomicAdd(&acc[g * HH + lane * 4 + 1], v.y);
        atomicAdd(&acc[g * HH + lane * 4 + 2], v.z);
        atomicAdd(&acc[g * HH + lane * 4 + 3], v.w);
        if (lane == 0) atomicAdd(&cnt[g], 1.f);
    }
    __syncthreads();

    for (int i = tid; i < BB * HH; i += blockDim.x)
        if (acc[i] != 0.f) atomicAdd(&gsub[i], acc[i]);
    if (tid < BB && cnt[tid] != 0.f) atomicAdd(&gcnt[tid], cnt[tid]);
}

__global__ void final_kernel(const float* __restrict__ gsub,
                             const float* __restrict__ gcnt,
                             const float* __restrict__ Wp,
                             const float* __restrict__ bp,
                             float* __restrict__ out)
{
    int t = threadIdx.x;
    if (t >= BB * OUTD) return;
    int b = t >> 1, o = t & 1;
    float c = fmaxf(gcnt[b], 1.f);
    float s = 0.f;
    #pragma unroll 8
    for (int h = 0; h < HH; h++) s = fmaf(gsub[b * HH + h], Wp[h * OUTD + o], s);
    out[t] = s / c + bp[o];
}

// ---------------- persistent stream/event resources ----------------
static cudaStream_t g_s1 = nullptr;
static cudaEvent_t  g_ev[8];

// ---------------- host orchestration: two-stream fork/join ----------------
extern "C" void kernel_launch(void* const* d_in, const int* in_sizes, int n_in,
                              void* d_out, int out_size)
{
    const float* x    = (const float*)d_in[0];
    const int*   ei   = (const int*)  d_in[1];
    const float* ew   = (const float*)d_in[2];
    const float* lx0i = (const float*)d_in[3];
    const int*   c2o  = (const int*)  d_in[4];
    const int*   lei  = (const int*)  d_in[5];
    const float* lev  = (const float*)d_in[6];
    const int*   midx = (const int*)  d_in[7];
    const int*   mgid = (const int*)  d_in[8];
    const float* Wb    = (const float*)d_in[10];
    const float* bb    = (const float*)d_in[11];
    const float* Wl    = (const float*)d_in[12];
    const float* bl    = (const float*)d_in[13];
    const float* Wbase = (const float*)d_in[14];
    const float* bbase = (const float*)d_in[15];
    const float* Wloc  = (const float*)d_in[16];
    const float* bloc  = (const float*)d_in[17];
    const float* Wp    = (const float*)d_in[18];
    const float* bp    = (const float*)d_in[19];
    float* out = (float*)d_out;

    const int N  = in_sizes[0] / HH;
    const int M  = in_sizes[3] / HH;
    const int E  = in_sizes[1] / 2;
    const int EL = in_sizes[5] / 2;
    const int K  = in_sizes[7];
    const int L  = in_sizes[14] / (HH * HH);

    if (!g_s1) {
        cudaStreamCreateWithFlags(&g_s1, cudaStreamNonBlocking);
        for (int i = 0; i < 8; i++)
            cudaEventCreateWithFlags(&g_ev[i], cudaEventDisableTiming);
    }
    cudaStream_t D = 0, S = g_s1;

    float *bx0, *bx1, *bagg, *lxA, *lxB, *lagg, *sub, *cntp;
    cudaGetSymbolAddress((void**)&bx0,  g_base_x0);
    cudaGetSymbolAddress((void**)&bx1,  g_base_x1);
    cudaGetSymbolAddress((void**)&bagg, g_base_agg);
    cudaGetSymbolAddress((void**)&lxA,  g_local_x0);
    cudaGetSymbolAddress((void**)&lxB,  g_local_x1);
    cudaGetSymbolAddress((void**)&lagg, g_local_agg);
    cudaGetSymbolAddress((void**)&sub,  g_sub);
    cudaGetSymbolAddress((void**)&cntp, g_cnt);

    int *csr_cnt, *csr_ptr, *csr_fill, *csr_src, *chunks;
    float* csr_w;
    cudaGetSymbolAddress((void**)&csr_cnt,  g_csr_cnt);
    cudaGetSymbolAddress((void**)&csr_ptr,  g_csr_ptr);
    cudaGetSymbolAddress((void**)&csr_fill, g_csr_fill);
    cudaGetSymbolAddress((void**)&csr_src,  g_csr_src);
    cudaGetSymbolAddress((void**)&csr_w,    g_csr_w);
    cudaGetSymbolAddress((void**)&chunks,   g_chunks);

    int*   ptr_b  = csr_ptr;            int*   ptr_l  = csr_ptr + (NN + 1);
    int*   fill_b = csr_fill;           int*   fill_l = csr_fill + NN;
    int*   src_b  = csr_src;            int*   src_l  = csr_src + EMAX;
    float* w_b    = csr_w;              float* w_l    = csr_w + EMAX;

    cudaFuncSetAttribute(gemm128_bias_relu<false>,
                         cudaFuncAttributeMaxDynamicSharedMemorySize, (int)GEMM_SMEM);
    cudaFuncSetAttribute(gemm128_bias_relu<true>,
                         cudaFuncAttributeMaxDynamicSharedMemorySize, (int)GEMM_SMEM);

    const int tiles_N = N / 64;
    const int tiles_M = M / 64;
    const int ET = E + EL;
    const int etb = (ET + 255) / 256;
    const int spmm_blocks_N = (N * 32 + 255) / 256;
    const int spmm_blocks_M = (M * 32 + 255) / 256;

    // ---- fork S from D ----
    cudaEventRecord(g_ev[0], D);
    cudaStreamWaitEvent(S, g_ev[0], 0);

    // ---- S: input projections (FMA-bound) ----
    gemm128_bias_relu<false><<<GEMM_GRID, 256, GEMM_SMEM, S>>>(
        x,    Wb, bb, bx0, nullptr, nullptr, tiles_N);
    cudaEventRecord(g_ev[1], S);   // base_x0 ready
    gemm128_bias_relu<false><<<GEMM_GRID, 256, GEMM_SMEM, S>>>(
        lx0i, Wl, bl, lxA, nullptr, nullptr, tiles_M);

    // ---- D: CSR build, both graphs fused per phase ----
    cudaMemsetAsync(csr_cnt,  0, 2 * NN * sizeof(int), D);
    cudaMemsetAsync(csr_fill, 0, 2 * NN * sizeof(int), D);
    hist2_kernel<<<etb, 256, 0, D>>>(ei + E, E, lei + EL, EL, csr_cnt);
    chunksum_kernel<<<512, 256, 0, D>>>(csr_cnt, chunks);
    scan2_kernel<<<2, 256, 0, D>>>(chunks, ptr_b, ptr_l, N);
    write_ptr2_kernel<<<512, 256, 0, D>>>(csr_cnt, chunks, ptr_b, ptr_l);
    scatter2_kernel<<<etb, 256, 0, D>>>(ei, E, ew, lei, EL, lev,
                                        ptr_b, fill_b, src_b, w_b,
                                        ptr_l, fill_l, src_l, w_l);
    cudaEventRecord(g_ev[2], D);   // both CSRs ready

    cudaStreamWaitEvent(S, g_ev[2], 0);   // S needs local CSR
    cudaStreamWaitEvent(D, g_ev[1], 0);   // D needs base_x0

    // ---- layer loop: base chain on D, local chain on S ----
    float* b_in = bx0; float* b_out = bx1;
    float* l_in = lxA; float* l_out = lxB;
    for (int l = 0; l < L; l++) {
        spmm_csr<<<spmm_blocks_N, 256, 0, D>>>(b_in, ptr_b, src_b, w_b, bagg, N);
        gemm128_bias_relu<false><<<GEMM_GRID, 256, GEMM_SMEM, D>>>(
            bagg, Wbase + (size_t)l * HH * HH, bbase + (size_t)l * HH, b_out,
            nullptr, nullptr, tiles_N);
        cudaEventRecord(g_ev[4 + l], D);

        spmm_csr<<<spmm_blocks_M, 256, 0, S>>>(l_in, ptr_l, src_l, w_l, lagg, M);
        cudaStreamWaitEvent(S, g_ev[4 + l], 0);
        gemm128_bias_relu<true><<<GEMM_GRID, 256, GEMM_SMEM, S>>>(
            lagg, Wloc + (size_t)l * HH * HH, bloc + (size_t)l * HH, l_out,
            b_out, c2o, tiles_M);

        float* t;
        t = b_in; b_in = b_out; b_out = t;
        t = l_in; l_in = l_out; l_out = t;
    }

    // ---- S: pooling + final projection ----
    cudaMemsetAsync(sub,  0, BB * HH * sizeof(float), S);
    cudaMemsetAsync(cntp, 0, BB * sizeof(float), S);
    const int pool_blocks = 128;
    const int entries_per_block = (K + pool_blocks - 1) / pool_blocks;
    pool_kernel<<<pool_blocks, 256, 0, S>>>(l_in, midx, mgid, sub, cntp, K, entries_per_block);
    final_kernel<<<1, 128, 0, S>>>(sub, cntp, Wp, bp, out);

    // ---- join ----
    cudaEventRecord(g_ev[7], S);
    cudaStreamWaitEvent(D, g_ev[7], 0);
}

// round 16
// speedup vs baseline: 1.6920x; 1.0084x over previous
#include <cuda_runtime.h>
#include <cuda_bf16.h>
#include <cstdint>

// ---------------- problem constants ----------------
#define NN   65536
#define MM   65536
#define HH   128
#define BB   64
#define OUTD 2
#define ALPHA 0.9f
#define EMAX (1 << 20)
#define GEMM_GRID 296          // 148 SMs x 2 CTAs (persistent)

// ---------------- device scratch ----------------
__device__ float g_base_x0 [(size_t)NN * HH];
__device__ float g_base_x1 [(size_t)NN * HH];
__device__ float g_base_agg[(size_t)NN * HH];
__device__ float g_local_x0[(size_t)MM * HH];
__device__ float g_local_x1[(size_t)MM * HH];
__device__ float g_local_agg[(size_t)MM * HH];
__device__ float g_sub[BB * HH];
__device__ float g_cnt[BB];

// bf16 mirrors of the activation buffers (gather operand for spmm)
__device__ __nv_bfloat16 g_base_xb0 [(size_t)NN * HH];
__device__ __nv_bfloat16 g_base_xb1 [(size_t)NN * HH];
__device__ __nv_bfloat16 g_local_xb0[(size_t)MM * HH];
__device__ __nv_bfloat16 g_local_xb1[(size_t)MM * HH];

__device__ int   g_csr_cnt [2][NN];
__device__ int   g_csr_ptr [2][NN + 1];
__device__ int   g_csr_fill[2][NN];
__device__ int   g_csr_src [2][EMAX];
__device__ float g_csr_w   [2][EMAX];
__device__ int   g_chunks  [2][256];

// ---------------- persistent GEMM: C = relu(A' @ W + bias), dual fp32+bf16 output ----------------
#define GEMM_SMEM ((128 * 64 + 128 * 128) * sizeof(float))   // 98304 B

__device__ __forceinline__ void ffma2(unsigned long long& d,
                                      unsigned long long a,
                                      unsigned long long b)
{
    asm("fma.rn.f32x2 %0, %1, %2, %0;" : "+l"(d) : "l"(a), "l"(b));
}

__device__ __forceinline__ unsigned long long dup_reg(float x)
{
    unsigned long long r;
    asm("mov.b64 %0, {%1, %1};" : "=l"(r) : "r"(__float_as_uint(x)));
    return r;
}

__device__ __forceinline__ uint32_t pack_bf16(float a, float b)
{
    __nv_bfloat162 h = __floats2bfloat162_rn(a, b);
    return *(uint32_t*)&h;
}

template<bool MIX>
__global__ void __launch_bounds__(256, 2)
gemm128_bias_relu(const float* __restrict__ A,
                  const float* __restrict__ W,
                  const float* __restrict__ bias,
                  float* __restrict__ C,
                  __nv_bfloat16* __restrict__ Cb,   // bf16 mirror
                  const float* __restrict__ BX,
                  const int* __restrict__ c2o,
                  int n_tiles)
{
    extern __shared__ float smem[];
    float* As = smem;                // [128][64]   As[k][r ^ swz(k)]
    float* Ws = smem + 128 * 64;     // [128][128]  Ws[k][col]

    const int tid = threadIdx.x;

    // ---- stage W ONCE per persistent CTA ----
    {
        const float4* W4  = (const float4*)W;
        float4*       Ws4 = (float4*)Ws;
        #pragma unroll
        for (int i = 0; i < 16; i++) Ws4[tid + 256 * i] = W4[tid + 256 * i];
    }

    const int j  = tid & 15;
    const int tr = (tid >> 4) * 4;
    const int c0 = 4 * j;
    const int c1 = 64 + 4 * j;
    float4 bv0 = *(const float4*)&bias[c0];
    float4 bv1 = *(const float4*)&bias[c1];

    for (int t = blockIdx.x; t < n_tiles; t += GEMM_GRID) {
        const int row0 = t * 64;

        // ---- stage A tile transposed + swizzled (optional alpha-mix) ----
        {
            const float4* A4 = (const float4*)(A + (size_t)row0 * HH);
            #pragma unroll
            for (int i = 0; i < 8; i++) {
                int idx = tid + 256 * i;      // = r*32 + k4
                int r   = idx >> 5;           // 0..63
                int k4  = idx & 31;
                float4 v = A4[idx];
                if (MIX) {
                    int o = __ldg(&c2o[row0 + r]);
                    float4 b = *(const float4*)&BX[(size_t)o * HH + k4 * 4];
                    v.x = ALPHA * v.x + (1.0f - ALPHA) * b.x;
                    v.y = ALPHA * v.y + (1.0f - ALPHA) * b.y;
                    v.z = ALPHA * v.z + (1.0f - ALPHA) * b.z;
                    v.w = ALPHA * v.w + (1.0f - ALPHA) * b.w;
                }
                int rs = r ^ (4 * (k4 & 15));
                As[(4 * k4 + 0) * 64 + rs] = v.x;
                As[(4 * k4 + 1) * 64 + rs] = v.y;
                As[(4 * k4 + 2) * 64 + rs] = v.z;
                As[(4 * k4 + 3) * 64 + rs] = v.w;
            }
        }
        __syncthreads();

        unsigned long long acc2[4][4];
        #pragma unroll
        for (int m = 0; m < 4; m++)
            #pragma unroll
            for (int p = 0; p < 4; p++) acc2[m][p] = 0ull;

        #pragma unroll 4
        for (int k = 0; k < 128; k++) {
            const int ab = tr ^ (4 * ((k >> 2) & 15));
            float4 a0 = *(const float4*)&As[k * 64 + ab];
            ulonglong2 w0 = *(const ulonglong2*)&Ws[k * 128 + c0];
            ulonglong2 w1 = *(const ulonglong2*)&Ws[k * 128 + c1];

            unsigned long long a2[4];
            a2[0] = dup_reg(a0.x); a2[1] = dup_reg(a0.y);
            a2[2] = dup_reg(a0.z); a2[3] = dup_reg(a0.w);
            unsigned long long wv[4] = {w0.x, w0.y, w1.x, w1.y};

            #pragma unroll
            for (int m = 0; m < 4; m++)
                #pragma unroll
                for (int p = 0; p < 4; p++)
                    ffma2(acc2[m][p], a2[m], wv[p]);
        }

        #pragma unroll
        for (int m = 0; m < 4; m++) {
            float2 p0 = *(float2*)&acc2[m][0];
            float2 p1 = *(float2*)&acc2[m][1];
            float2 p2 = *(float2*)&acc2[m][2];
            float2 p3 = *(float2*)&acc2[m][3];
            float4 o0, o1;
            o0.x = fmaxf(p0.x + bv0.x, 0.f);
            o0.y = fmaxf(p0.y + bv0.y, 0.f);
            o0.z = fmaxf(p1.x + bv0.z, 0.f);
            o0.w = fmaxf(p1.y + bv0.w, 0.f);
            o1.x = fmaxf(p2.x + bv1.x, 0.f);
            o1.y = fmaxf(p2.y + bv1.y, 0.f);
            o1.z = fmaxf(p3.x + bv1.z, 0.f);
            o1.w = fmaxf(p3.y + bv1.w, 0.f);
            const size_t rb = (size_t)(row0 + tr + m) * HH;
            *(float4*)&C[rb + c0] = o0;
            *(float4*)&C[rb + c1] = o1;
            // bf16 mirror (8B stores, 8-aligned since c0,c1 are multiples of 4)
            uint2 u0, u1;
            u0.x = pack_bf16(o0.x, o0.y); u0.y = pack_bf16(o0.z, o0.w);
            u1.x = pack_bf16(o1.x, o1.y); u1.y = pack_bf16(o1.z, o1.w);
            *(uint2*)&Cb[rb + c0] = u0;
            *(uint2*)&Cb[rb + c1] = u1;
        }
        __syncthreads();   // protect As before next tile's staging
    }
}

// ---------------- CSR build, fused across both graphs ----------------
__global__ void hist2_kernel(const int* __restrict__ dst_b, int E,
                             const int* __restrict__ dst_l, int EL,
                             int* __restrict__ cnt)
{
    int e = blockIdx.x * blockDim.x + threadIdx.x;
    if (e < E)            atomicAdd(&cnt[dst_b[e]], 1);
    else if (e < E + EL)  atomicAdd(&cnt[NN + dst_l[e - E]], 1);
}

__global__ void chunksum_kernel(const int* __restrict__ cnt, int* __restrict__ chunks)
{
    const int tid = threadIdx.x, lane = tid & 31, w = tid >> 5;
    __shared__ int wsum[8];
    int v = cnt[blockIdx.x * 256 + tid];
    #pragma unroll
    for (int off = 16; off > 0; off >>= 1) v += __shfl_down_sync(0xffffffffu, v, off);
    if (lane == 0) wsum[w] = v;
    __syncthreads();
    if (tid == 0) {
        int s = 0;
        #pragma unroll
        for (int i = 0; i < 8; i++) s += wsum[i];
        chunks[blockIdx.x] = s;
    }
}

__global__ void scan2_kernel(int* __restrict__ chunks,
                             int* __restrict__ ptr_b, int* __restrict__ ptr_l, int n)
{
    const int g   = blockIdx.x;
    const int tid = threadIdx.x, lane = tid & 31, w = tid >> 5;
    int* ch = chunks + g * 256;
    __shared__ int wsum[8];
    int v = ch[tid];
    int inc = v;
    #pragma unroll
    for (int off = 1; off < 32; off <<= 1) {
        int t = __shfl_up_sync(0xffffffffu, inc, off);
        if (lane >= off) inc += t;
    }
    if (lane == 31) wsum[w] = inc;
    __syncthreads();
    if (w == 0 && lane < 8) {
        int s = wsum[lane];
        #pragma unroll
        for (int off = 1; off < 8; off <<= 1) {
            int t = __shfl_up_sync(0x000000ffu, s, off);
            if (lane >= off) s += t;
        }
        wsum[lane] = s;
    }
    __syncthreads();
    int excl = inc - v + (w > 0 ? wsum[w - 1] : 0);
    ch[tid] = excl;
    if (tid == 255) {
        if (g == 0) ptr_b[n] = excl + v; else ptr_l[n] = excl + v;
    }
}

__global__ void write_ptr2_kernel(const int* __restrict__ cnt,
                                  const int* __restrict__ chunks,
                                  int* __restrict__ ptr_b,
                                  int* __restrict__ ptr_l)
{
    const int tid = threadIdx.x, lane = tid & 31, w = tid >> 5;
    __shared__ int wsum[8];
    const int gid = blockIdx.x * 256 + tid;
    int v = cnt[gid];
    int inc = v;
    #pragma unroll
    for (int off = 1; off < 32; off <<= 1) {
        int t = __shfl_up_sync(0xffffffffu, inc, off);
        if (lane >= off) inc += t;
    }
    if (lane == 31) wsum[w] = inc;
    __syncthreads();
    if (w == 0 && lane < 8) {
        int s = wsum[lane];
        #pragma unroll
        for (int off = 1; off < 8; off <<= 1) {
            int t = __shfl_up_sync(0x000000ffu, s, off);
            if (lane >= off) s += t;
        }
        wsum[lane] = s;
    }
    __syncthreads();
    int val = inc - v + (w > 0 ? wsum[w - 1] : 0) + chunks[blockIdx.x];
    if (gid < NN) ptr_b[gid] = val;
    else          ptr_l[gid - NN] = val;
}

__global__ void scatter2_kernel(const int* __restrict__ ei,  int E,
                                const float* __restrict__ ew,
                                const int* __restrict__ lei, int EL,
                                const float* __restrict__ lev,
                                const int* __restrict__ ptr_b, int* __restrict__ fill_b,
                                int* __restrict__ src_b, float* __restrict__ w_b,
                                const int* __restrict__ ptr_l, int* __restrict__ fill_l,
                                int* __restrict__ src_l, float* __restrict__ w_l)
{
    int e = blockIdx.x * blockDim.x + threadIdx.x;
    if (e < E) {
        int d = ei[E + e];
        int pos = ptr_b[d] + atomicAdd(&fill_b[d], 1);
        src_b[pos] = ei[e];
        w_b[pos]   = ew[e];
    } else if (e < E + EL) {
        int ee = e - E;
        int d = lei[EL + ee];
        int pos = ptr_l[d] + atomicAdd(&fill_l[d], 1);
        src_l[pos] = lei[ee];
        w_l[pos]   = lev[ee];
    }
}

// ---------------- SpMM over CSR, bf16 gather / fp32 accumulate ----------------
__global__ void __launch_bounds__(256, 8)
spmm_csr(const __nv_bfloat16* __restrict__ X,
         const int* __restrict__ ptr,
         const int* __restrict__ csrc,
         const float* __restrict__ cw,
         float* __restrict__ Y, int n)
{
    const int lane = threadIdx.x & 31;
    const int row  = (blockIdx.x * blockDim.x + threadIdx.x) >> 5;
    if (row >= n) return;
    const int beg = ptr[row];
    const int end = ptr[row + 1];
    float4 acc0 = make_float4(0.f, 0.f, 0.f, 0.f);
    float4 acc1 = make_float4(0.f, 0.f, 0.f, 0.f);
    int i = beg;
    for (; i + 1 < end; i += 2) {
        int   s0 = csrc[i];     float w0 = cw[i];
        int   s1 = csrc[i + 1]; float w1 = cw[i + 1];
        uint2 v0 = *(const uint2*)&X[(size_t)s0 * HH + lane * 4];
        uint2 v1 = *(const uint2*)&X[(size_t)s1 * HH + lane * 4];
        float2 a = __bfloat1622float2(*(__nv_bfloat162*)&v0.x);
        float2 b = __bfloat1622float2(*(__nv_bfloat162*)&v0.y);
        float2 c = __bfloat1622float2(*(__nv_bfloat162*)&v1.x);
        float2 d = __bfloat1622float2(*(__nv_bfloat162*)&v1.y);
        acc0.x = fmaf(w0, a.x, acc0.x); acc0.y = fmaf(w0, a.y, acc0.y);
        acc0.z = fmaf(w0, b.x, acc0.z); acc0.w = fmaf(w0, b.y, acc0.w);
        acc1.x = fmaf(w1, c.x, acc1.x); acc1.y = fmaf(w1, c.y, acc1.y);
        acc1.z = fmaf(w1, d.x, acc1.z); acc1.w = fmaf(w1, d.y, acc1.w);
    }
    if (i < end) {
        int s = csrc[i]; float w = cw[i];
        uint2 v = *(const uint2*)&X[(size_t)s * HH + lane * 4];
        float2 a = __bfloat1622float2(*(__nv_bfloat162*)&v.x);
        float2 b = __bfloat1622float2(*(__nv_bfloat162*)&v.y);
        acc0.x = fmaf(w, a.x, acc0.x); acc0.y = fmaf(w, a.y, acc0.y);
        acc0.z = fmaf(w, b.x, acc0.z); acc0.w = fmaf(w, b.y, acc0.w);
    }
    acc0.x += acc1.x; acc0.y += acc1.y; acc0.z += acc1.z; acc0.w += acc1.w;
    *(float4*)&Y[(size_t)row * HH + lane * 4] = acc0;
}

// input projection source is fp32 (model inputs) -> plain copy spmm not needed;
// projections read A directly in the GEMM, so no fp32 spmm variant required.

// ---------------- pooling ----------------
__global__ void pool_kernel(const float* __restrict__ lx,
                            const int* __restrict__ midx,
                            const int* __restrict__ mgid,
                            float* __restrict__ gsub,
                            float* __restrict__ gcnt,
                            int K, int entries_per_block)
{
    __shared__ float acc[BB * HH];
    __shared__ float cnt[BB];
    const int tid = threadIdx.x;
    for (int i = tid; i < BB * HH; i += blockDim.x) acc[i] = 0.f;
    if (tid < BB) cnt[tid] = 0.f;
    __syncthreads();

    const int warp = tid >> 5;
    const int lane = tid & 31;
    const int base = blockIdx.x * entries_per_block;
    const int end  = min(base + entries_per_block, K);
    for (int k = base + warp; k < end; k += (int)(blockDim.x >> 5)) {
        int idx = midx[k];
        int g   = mgid[k];
        float4 v = *(const float4*)&lx[(size_t)idx * HH + lane * 4];
        atomicAdd(&acc[g * HH + lane * 4 + 0], v.x);
        atomicAdd(&acc[g * HH + lane * 4 + 1], v.y);
        atomicAdd(&acc[g * HH + lane * 4 + 2], v.z);
        atomicAdd(&acc[g * HH + lane * 4 + 3], v.w);
        if (lane == 0) atomicAdd(&cnt[g], 1.f);
    }
    __syncthreads();

    for (int i = tid; i < BB * HH; i += blockDim.x)
        if (acc[i] != 0.f) atomicAdd(&gsub[i], acc[i]);
    if (tid < BB && cnt[tid] != 0.f) atomicAdd(&gcnt[tid], cnt[tid]);
}

__global__ void final_kernel(const float* __restrict__ gsub,
                             const float* __restrict__ gcnt,
                             const float* __restrict__ Wp,
                             const float* __restrict__ bp,
                             float* __restrict__ out)
{
    int t = threadIdx.x;
    if (t >= BB * OUTD) return;
    int b = t >> 1, o = t & 1;
    float c = fmaxf(gcnt[b], 1.f);
    float s = 0.f;
    #pragma unroll 8
    for (int h = 0; h < HH; h++) s = fmaf(gsub[b * HH + h], Wp[h * OUTD + o], s);
    out[t] = s / c + bp[o];
}

// ---------------- persistent stream/event resources ----------------
static cudaStream_t g_s1 = nullptr;
static cudaEvent_t  g_ev[8];

// ---------------- host orchestration: two-stream fork/join ----------------
extern "C" void kernel_launch(void* const* d_in, const int* in_sizes, int n_in,
                              void* d_out, int out_size)
{
    const float* x    = (const float*)d_in[0];
    const int*   ei   = (const int*)  d_in[1];
    const float* ew   = (const float*)d_in[2];
    const float* lx0i = (const float*)d_in[3];
    const int*   c2o  = (const int*)  d_in[4];
    const int*   lei  = (const int*)  d_in[5];
    const float* lev  = (const float*)d_in[6];
    const int*   midx = (const int*)  d_in[7];
    const int*   mgid = (const int*)  d_in[8];
    const float* Wb    = (const float*)d_in[10];
    const float* bb    = (const float*)d_in[11];
    const float* Wl    = (const float*)d_in[12];
    const float* bl    = (const float*)d_in[13];
    const float* Wbase = (const float*)d_in[14];
    const float* bbase = (const float*)d_in[15];
    const float* Wloc  = (const float*)d_in[16];
    const float* bloc  = (const float*)d_in[17];
    const float* Wp    = (const float*)d_in[18];
    const float* bp    = (const float*)d_in[19];
    float* out = (float*)d_out;

    const int N  = in_sizes[0] / HH;
    const int M  = in_sizes[3] / HH;
    const int E  = in_sizes[1] / 2;
    const int EL = in_sizes[5] / 2;
    const int K  = in_sizes[7];
    const int L  = in_sizes[14] / (HH * HH);

    if (!g_s1) {
        cudaStreamCreateWithFlags(&g_s1, cudaStreamNonBlocking);
        for (int i = 0; i < 8; i++)
            cudaEventCreateWithFlags(&g_ev[i], cudaEventDisableTiming);
    }
    cudaStream_t D = 0, S = g_s1;

    float *bx0, *bx1, *bagg, *lxA, *lxB, *lagg, *sub, *cntp;
    cudaGetSymbolAddress((void**)&bx0,  g_base_x0);
    cudaGetSymbolAddress((void**)&bx1,  g_base_x1);
    cudaGetSymbolAddress((void**)&bagg, g_base_agg);
    cudaGetSymbolAddress((void**)&lxA,  g_local_x0);
    cudaGetSymbolAddress((void**)&lxB,  g_local_x1);
    cudaGetSymbolAddress((void**)&lagg, g_local_agg);
    cudaGetSymbolAddress((void**)&sub,  g_sub);
    cudaGetSymbolAddress((void**)&cntp, g_cnt);

    __nv_bfloat16 *bxb0, *bxb1, *lxbA, *lxbB;
    cudaGetSymbolAddress((void**)&bxb0, g_base_xb0);
    cudaGetSymbolAddress((void**)&bxb1, g_base_xb1);
    cudaGetSymbolAddress((void**)&lxbA, g_local_xb0);
    cudaGetSymbolAddress((void**)&lxbB, g_local_xb1);

    int *csr_cnt, *csr_ptr, *csr_fill, *csr_src, *chunks;
    float* csr_w;
    cudaGetSymbolAddress((void**)&csr_cnt,  g_csr_cnt);
    cudaGetSymbolAddress((void**)&csr_ptr,  g_csr_ptr);
    cudaGetSymbolAddress((void**)&csr_fill, g_csr_fill);
    cudaGetSymbolAddress((void**)&csr_src,  g_csr_src);
    cudaGetSymbolAddress((void**)&csr_w,    g_csr_w);
    cudaGetSymbolAddress((void**)&chunks,   g_chunks);

    int*   ptr_b  = csr_ptr;            int*   ptr_l  = csr_ptr + (NN + 1);
    int*   fill_b = csr_fill;           int*   fill_l = csr_fill + NN;
    int*   src_b  = csr_src;            int*   src_l  = csr_src + EMAX;
    float* w_b    = csr_w;              float* w_l    = csr_w + EMAX;

    cudaFuncSetAttribute(gemm128_bias_relu<false>,
                         cudaFuncAttributeMaxDynamicSharedMemorySize, (int)GEMM_SMEM);
    cudaFuncSetAttribute(gemm128_bias_relu<true>,
                         cudaFuncAttributeMaxDynamicSharedMemorySize, (int)GEMM_SMEM);

    const int tiles_N = N / 64;
    const int tiles_M = M / 64;
    const int ET = E + EL;
    const int etb = (ET + 255) / 256;
    const int spmm_blocks_N = (N * 32 + 255) / 256;
    const int spmm_blocks_M = (M * 32 + 255) / 256;

    // ---- fork S from D ----
    cudaEventRecord(g_ev[0], D);
    cudaStreamWaitEvent(S, g_ev[0], 0);

    // ---- S: input projections ----
    gemm128_bias_relu<false><<<GEMM_GRID, 256, GEMM_SMEM, S>>>(
        x,    Wb, bb, bx0, bxb0, nullptr, nullptr, tiles_N);
    cudaEventRecord(g_ev[1], S);   // base_x0 (+bf16) ready
    gemm128_bias_relu<false><<<GEMM_GRID, 256, GEMM_SMEM, S>>>(
        lx0i, Wl, bl, lxA, lxbA, nullptr, nullptr, tiles_M);

    // ---- D: CSR build, both graphs fused per phase ----
    cudaMemsetAsync(csr_cnt,  0, 2 * NN * sizeof(int), D);
    cudaMemsetAsync(csr_fill, 0, 2 * NN * sizeof(int), D);
    hist2_kernel<<<etb, 256, 0, D>>>(ei + E, E, lei + EL, EL, csr_cnt);
    chunksum_kernel<<<512, 256, 0, D>>>(csr_cnt, chunks);
    scan2_kernel<<<2, 256, 0, D>>>(chunks, ptr_b, ptr_l, N);
    write_ptr2_kernel<<<512, 256, 0, D>>>(csr_cnt, chunks, ptr_b, ptr_l);
    scatter2_kernel<<<etb, 256, 0, D>>>(ei, E, ew, lei, EL, lev,
                                        ptr_b, fill_b, src_b, w_b,
                                        ptr_l, fill_l, src_l, w_l);
    cudaEventRecord(g_ev[2], D);   // both CSRs ready

    cudaStreamWaitEvent(S, g_ev[2], 0);   // S needs local CSR
    cudaStreamWaitEvent(D, g_ev[1], 0);   // D needs base_x0

    // ---- layer loop: base chain on D, local chain on S ----
    float* b_in = bx0;  float* b_out = bx1;
    float* l_in = lxA;  float* l_out = lxB;
    __nv_bfloat16* bb_in = bxb0;  __nv_bfloat16* bb_out = bxb1;
    __nv_bfloat16* lb_in = lxbA;  __nv_bfloat16* lb_out = lxbB;
    for (int l = 0; l < L; l++) {
        spmm_csr<<<spmm_blocks_N, 256, 0, D>>>(bb_in, ptr_b, src_b, w_b, bagg, N);
        gemm128_bias_relu<false><<<GEMM_GRID, 256, GEMM_SMEM, D>>>(
            bagg, Wbase + (size_t)l * HH * HH, bbase + (size_t)l * HH, b_out, bb_out,
            nullptr, nullptr, tiles_N);
        cudaEventRecord(g_ev[4 + l], D);

        spmm_csr<<<spmm_blocks_M, 256, 0, S>>>(lb_in, ptr_l, src_l, w_l, lagg, M);
        cudaStreamWaitEvent(S, g_ev[4 + l], 0);
        gemm128_bias_relu<true><<<GEMM_GRID, 256, GEMM_SMEM, S>>>(
            lagg, Wloc + (size_t)l * HH * HH, bloc + (size_t)l * HH, l_out, lb_out,
            b_out, c2o, tiles_M);

        float* t;
        t = b_in; b_in = b_out; b_out = t;
        t = l_in; l_in = l_out; l_out = t;
        __nv_bfloat16* tb;
        tb = bb_in; bb_in = bb_out; bb_out = tb;
        tb = lb_in; lb_in = lb_out; lb_out = tb;
    }

    // ---- S: pooling (fp32 activations) + final projection ----
    cudaMemsetAsync(sub,  0, BB * HH * sizeof(float), S);
    cudaMemsetAsync(cntp, 0, BB * sizeof(float), S);
    const int pool_blocks = 128;
    const int entries_per_block = (K + pool_blocks - 1) / pool_blocks;
    pool_kernel<<<pool_blocks, 256, 0, S>>>(l_in, midx, mgid, sub, cntp, K, entries_per_block);
    final_kernel<<<1, 128, 0, S>>>(sub, cntp, Wp, bp, out);

    // ---- join ----
    cudaEventRecord(g_ev[7], S);
    cudaStreamWaitEvent(D, g_ev[7], 0);
}